// round 6
// baseline (speedup 1.0000x reference)
#include <cuda_runtime.h>
#include <cuda_fp16.h>
#include <math.h>
#include <stdint.h>

// ---------------- problem constants ----------------
#define B_   16384
#define NF_  50
#define KE_  16
#define D_   800     // NF_*KE_
#define H_   400
#define KP1  832     // padded K for GEMM1 (26 * 32)
#define KP2  448     // padded K for GEMM2 (14 * 32)
#define NP_  448     // padded N (= 7 * 64)
#define TM   128
#define TN   64
#define BKC  32

// ---------------- scratch globals (fp16 hi/lo splits) ----------------
__device__ __half g_Xhi [B_ * KP1];
__device__ __half g_Xlo [B_ * KP1];
__device__ __half g_W0hi[NP_ * KP1];   // W0^T hi  [448][832], rows>=400 zero
__device__ __half g_W0lo[NP_ * KP1];
__device__ __half g_W1hi[NP_ * KP2];   // W1^T hi  [448][448]
__device__ __half g_W1lo[NP_ * KP2];
__device__ __half g_H0hi[B_ * KP2];    // cols>=400 zeroed by GEMM1 epilogue
__device__ __half g_H0lo[B_ * KP2];
__device__ float g_H1[B_ * H_];
__device__ float g_ZP[B_];

// ---------------- PTX helpers ----------------
__device__ __forceinline__ uint32_t smem_u32(const void* p) {
    uint32_t a;
    asm("{ .reg .u64 t; cvta.to.shared.u64 t, %1; cvt.u32.u64 %0, t; }"
        : "=r"(a) : "l"(p));
    return a;
}

#define CP16(dst, src) \
    asm volatile("cp.async.cg.shared.global [%0], [%1], 16;" \
                 :: "r"(dst), "l"(src) : "memory")
#define CP_COMMIT() asm volatile("cp.async.commit_group;" ::: "memory")
#define CP_WAIT(n)  asm volatile("cp.async.wait_group %0;" :: "n"(n) : "memory")

#define LDSM4(r, addr) \
    asm volatile("ldmatrix.sync.aligned.m8n8.x4.shared.b16 {%0,%1,%2,%3}, [%4];" \
        : "=r"((r)[0]), "=r"((r)[1]), "=r"((r)[2]), "=r"((r)[3]) : "r"(addr))

// main term: f16 x f16 -> f32 accumulate
__device__ __forceinline__ void mma16f(float* c, const uint32_t* a,
                                       uint32_t b0, uint32_t b1) {
    asm volatile(
        "mma.sync.aligned.m16n8k16.row.col.f32.f16.f16.f32 "
        "{%0,%1,%2,%3}, {%4,%5,%6,%7}, {%8,%9}, {%0,%1,%2,%3};"
        : "+f"(c[0]), "+f"(c[1]), "+f"(c[2]), "+f"(c[3])
        : "r"(a[0]), "r"(a[1]), "r"(a[2]), "r"(a[3]), "r"(b0), "r"(b1));
}
// correction terms: f16 x f16 -> f16 accumulate (potentially double rate)
__device__ __forceinline__ void mma16h(uint32_t* c, const uint32_t* a,
                                       uint32_t b0, uint32_t b1) {
    asm volatile(
        "mma.sync.aligned.m16n8k16.row.col.f16.f16.f16.f16 "
        "{%0,%1}, {%2,%3,%4,%5}, {%6,%7}, {%0,%1};"
        : "+r"(c[0]), "+r"(c[1])
        : "r"(a[0]), "r"(a[1]), "r"(a[2]), "r"(a[3]), "r"(b0), "r"(b1));
}

__device__ __forceinline__ __half hhi(float x) { return __float2half_rn(x); }

// ---------------------------------------------------------------------------
// Kernel A: transpose+split  W[K][N] fp32 -> T{hi,lo}[NP][KP] fp16 (zero pad)
// ---------------------------------------------------------------------------
__global__ __launch_bounds__(256) void transpose_split(
    const float* __restrict__ W, __half* __restrict__ Thi,
    __half* __restrict__ Tlo, int K, int N, int KP, int NP)
{
    __shared__ float t[32][33];
    const int kt = blockIdx.x * 32;
    const int nt = blockIdx.y * 32;
    const int tx = threadIdx.x & 31;
    const int ty = threadIdx.x >> 5;   // 0..7

    #pragma unroll
    for (int i = 0; i < 4; i++) {
        const int k = kt + ty + i * 8;
        float v = 0.f;
        if (k < K && nt + tx < N) v = W[(size_t)k * N + nt + tx];
        t[ty + i * 8][tx] = v;
    }
    __syncthreads();
    #pragma unroll
    for (int i = 0; i < 4; i++) {
        const int n = nt + ty + i * 8;
        const int k = kt + tx;
        if (n < NP && k < KP) {
            const float v = t[tx][ty + i * 8];
            const __half h = hhi(v);
            Thi[(size_t)n * KP + k] = h;
            Tlo[(size_t)n * KP + k] = hhi(v - __half2float(h));
        }
    }
}

// ---------------------------------------------------------------------------
// Kernel B: gather + first-order + FM second-order + X hi/lo materialization
// ---------------------------------------------------------------------------
__global__ __launch_bounds__(256) void gather_fm_kernel(
    const int*   __restrict__ feats,
    const float* __restrict__ values,
    const float* __restrict__ weights,
    const float* __restrict__ embedding,
    const float* __restrict__ bias)
{
    const int b   = blockIdx.x;
    const int tid = threadIdx.x;
    const int base = b * NF_;

    __shared__ float s1s[KE_];
    __shared__ float s2s[KE_];
    __shared__ float fsum;

    if (tid < KE_) { s1s[tid] = 0.f; s2s[tid] = 0.f; }
    if (tid == KE_) fsum = 0.f;
    __syncthreads();

    float a1 = 0.f, a2 = 0.f, fw = 0.f;
    const int myk = tid & 15;

    for (int i = tid; i < D_; i += 256) {
        const int f = i >> 4;
        const int feat = feats[base + f];
        const float v = values[base + f];
        const float e = embedding[(size_t)feat * KE_ + (i & 15)];
        const __half h = hhi(e);
        g_Xhi[(size_t)b * KP1 + i] = h;
        g_Xlo[(size_t)b * KP1 + i] = hhi(e - __half2float(h));
        const float ev = e * v;
        a1 += ev;
        a2 += ev * ev;
        if ((i & 15) == 0) fw += weights[feat] * v;
    }
    if (tid < KP1 - D_) {   // zero K padding
        g_Xhi[(size_t)b * KP1 + D_ + tid] = __float2half(0.f);
        g_Xlo[(size_t)b * KP1 + D_ + tid] = __float2half(0.f);
    }
    atomicAdd(&s1s[myk], a1);
    atomicAdd(&s2s[myk], a2);
    if ((tid & 15) == 0) atomicAdd(&fsum, fw);
    __syncthreads();

    if (tid == 0) {
        float sec = 0.f;
        #pragma unroll
        for (int k = 0; k < KE_; k++) sec += s1s[k] * s1s[k] - s2s[k];
        g_ZP[b] = fsum + bias[0] + 0.5f * sec;
    }
}

// ---------------------------------------------------------------------------
// Kernel C: split-fp16 tensor GEMM. Main term f32-acc, corrections f16-acc.
// 2-stage cp.async double buffer (round-4 pipeline: best measured).
// ---------------------------------------------------------------------------
#define ASTR 40                 // smem row stride (fp16 units)
#define OFF_AH 0
#define OFF_AL 10240            // bytes
#define OFF_BH 20480
#define OFF_BL 25600
#define STAGE_BYTES 30720
#define SMEM_BYTES (2 * STAGE_BYTES)

__global__ __launch_bounds__(256) void gemm_mma(
    const __half* __restrict__ Ahi, const __half* __restrict__ Alo,
    const __half* __restrict__ Bh,  const __half* __restrict__ Bl,
    const float* __restrict__ biasp,
    int KP, int nchunks, int mode,
    float* __restrict__ outF,
    __half* __restrict__ outHi, __half* __restrict__ outLo)
{
    extern __shared__ char smem[];
    const uint32_t sbase = smem_u32(smem);

    const int tid  = threadIdx.x;
    const int lane = tid & 31;
    const int w    = tid >> 5;
    const int wm   = (w >> 1) << 5;   // warp M offset (0,32,64,96)
    const int wn   = (w & 1) << 5;    // warp N offset (0,32)
    const int grp  = lane >> 2;
    const int thg  = lane & 3;
    const int row0 = blockIdx.y * TM;
    const int col0 = blockIdx.x * TN;

    const int sub = lane >> 3;        // ldmatrix sub-tile select
    const int l8  = lane & 7;

    float    acc [2][4][4];           // f32 main accumulators
    uint32_t cacc[2][4][2];           // f16x2 correction accumulators
    #pragma unroll
    for (int i = 0; i < 2; i++)
        #pragma unroll
        for (int j = 0; j < 4; j++) {
            #pragma unroll
            for (int q = 0; q < 4; q++) acc[i][j][q] = 0.f;
            cacc[i][j][0] = 0u; cacc[i][j][1] = 0u;
        }

    auto load_chunk = [&](int c, int s) {
        const int k0 = c * BKC;
        const uint32_t stb = sbase + s * STAGE_BYTES;
        #pragma unroll
        for (int i = 0; i < 2; i++) {
            const int v  = tid + (i << 8);
            const int r  = v >> 2;
            const int c8 = (v & 3) << 3;
            const uint32_t so = (uint32_t)(r * ASTR + c8) * 2;
            const size_t g = (size_t)(row0 + r) * KP + k0 + c8;
            CP16(stb + OFF_AH + so, Ahi + g);
            CP16(stb + OFF_AL + so, Alo + g);
        }
        {
            const int r  = tid >> 2;
            const int c8 = (tid & 3) << 3;
            const uint32_t so = (uint32_t)(r * ASTR + c8) * 2;
            const size_t g = (size_t)(col0 + r) * KP + k0 + c8;
            CP16(stb + OFF_BH + so, Bh + g);
            CP16(stb + OFF_BL + so, Bl + g);
        }
        CP_COMMIT();
    };

    load_chunk(0, 0);

    for (int c = 0; c < nchunks; c++) {
        const int s = c & 1;
        if (c + 1 < nchunks) { load_chunk(c + 1, s ^ 1); CP_WAIT(1); }
        else                 { CP_WAIT(0); }
        __syncthreads();

        const uint32_t stb = sbase + s * STAGE_BYTES;
        #pragma unroll
        for (int kk = 0; kk < BKC; kk += 16) {
            uint32_t ah[2][4], al[2][4], bh[2][4], bl[2][4];
            #pragma unroll
            for (int i = 0; i < 2; i++) {
                const int row = wm + i * 16 + ((sub & 1) << 3) + l8;
                const int kc  = kk + ((sub >> 1) << 3);
                const uint32_t ad = stb + OFF_AH + (uint32_t)(row * ASTR + kc) * 2;
                LDSM4(ah[i], ad);
                LDSM4(al[i], ad + (OFF_AL - OFF_AH));
            }
            #pragma unroll
            for (int jj = 0; jj < 2; jj++) {
                const int row = wn + jj * 16 + ((sub >> 1) << 3) + l8;
                const int kc  = kk + ((sub & 1) << 3);
                const uint32_t bd = stb + OFF_BH + (uint32_t)(row * ASTR + kc) * 2;
                LDSM4(bh[jj], bd);
                LDSM4(bl[jj], bd + (OFF_BL - OFF_BH));
            }
            // main term, f32 acc: 8 independent accumulators
            #pragma unroll
            for (int i = 0; i < 2; i++)
                #pragma unroll
                for (int j = 0; j < 4; j++)
                    mma16f(acc[i][j], ah[i],
                           bh[j >> 1][(j & 1) * 2], bh[j >> 1][(j & 1) * 2 + 1]);
            // correction terms, f16 acc
            #pragma unroll
            for (int i = 0; i < 2; i++)
                #pragma unroll
                for (int j = 0; j < 4; j++)
                    mma16h(cacc[i][j], al[i],
                           bh[j >> 1][(j & 1) * 2], bh[j >> 1][(j & 1) * 2 + 1]);
            #pragma unroll
            for (int i = 0; i < 2; i++)
                #pragma unroll
                for (int j = 0; j < 4; j++)
                    mma16h(cacc[i][j], ah[i],
                           bl[j >> 1][(j & 1) * 2], bl[j >> 1][(j & 1) * 2 + 1]);
        }
        __syncthreads();
    }

    // ---- epilogue: combine main + correction, bias + relu, write out
    const float bv = *biasp;
    #pragma unroll
    for (int i = 0; i < 2; i++) {
        #pragma unroll
        for (int j = 0; j < 4; j++) {
            const int r = row0 + wm + i * 16 + grp;
            const int cc = col0 + wn + j * 8 + (thg << 1);
            #pragma unroll
            for (int half = 0; half < 2; half++) {
                const int rr = r + half * 8;
                const __half2 ch = *reinterpret_cast<const __half2*>(&cacc[i][j][half]);
                const float x0f = acc[i][j][half * 2]     + __half2float(__low2half(ch));
                const float x1f = acc[i][j][half * 2 + 1] + __half2float(__high2half(ch));
                const float x0r = fmaxf(x0f + bv, 0.f);
                const float x1r = fmaxf(x1f + bv, 0.f);
                if (mode == 0) {
                    const float x0 = (cc     < H_) ? x0r : 0.f;
                    const float x1 = (cc + 1 < H_) ? x1r : 0.f;
                    const __half h0 = hhi(x0), h1 = hhi(x1);
                    __half2 hp, lp;
                    hp.x = h0; hp.y = h1;
                    lp.x = hhi(x0 - __half2float(h0));
                    lp.y = hhi(x1 - __half2float(h1));
                    const size_t o = (size_t)rr * KP2 + cc;
                    *reinterpret_cast<__half2*>(outHi + o) = hp;
                    *reinterpret_cast<__half2*>(outLo + o) = lp;
                } else {
                    if (cc < H_) {
                        float2 q; q.x = x0r; q.y = x1r;
                        *reinterpret_cast<float2*>(outF + (size_t)rr * H_ + cc) = q;
                    }
                }
            }
        }
    }
}

// ---------------------------------------------------------------------------
// Kernel D: per-sample GEMV + relu + FM partial + sigmoid
// ---------------------------------------------------------------------------
__global__ __launch_bounds__(256) void final_kernel(
    const float* __restrict__ W2,
    const float* __restrict__ b2,
    float*       __restrict__ out)
{
    const int gw   = (blockIdx.x * blockDim.x + threadIdx.x) >> 5;
    const int lane = threadIdx.x & 31;
    if (gw >= B_) return;

    float s = 0.f;
    const float* h = &g_H1[(size_t)gw * H_];
    for (int j = lane * 4; j < H_; j += 128) {
        const float4 hv = *reinterpret_cast<const float4*>(&h[j]);
        const float4 wv = *reinterpret_cast<const float4*>(&W2[j]);
        s += hv.x * wv.x + hv.y * wv.y + hv.z * wv.z + hv.w * wv.w;
    }
    #pragma unroll
    for (int o = 16; o; o >>= 1) s += __shfl_xor_sync(0xffffffffu, s, o);

    if (lane == 0) {
        const float hi = fmaxf(s + b2[0], 0.f);
        const float z  = g_ZP[gw] + hi;
        out[gw] = 1.f / (1.f + expf(-z));
    }
}

// ---------------------------------------------------------------------------
extern "C" void kernel_launch(void* const* d_in, const int* in_sizes, int n_in,
                              void* d_out, int out_size)
{
    const int*   feats   = (const int*)  d_in[1];
    const float* values  = (const float*)d_in[2];
    const float* bias    = (const float*)d_in[3];
    const float* weights = (const float*)d_in[4];
    const float* emb     = (const float*)d_in[5];
    const float* W0      = (const float*)d_in[6];
    const float* b0      = (const float*)d_in[7];
    const float* W1      = (const float*)d_in[8];
    const float* b1      = (const float*)d_in[9];
    const float* W2      = (const float*)d_in[10];
    const float* b2      = (const float*)d_in[11];
    float* out = (float*)d_out;

    __half *Xhi, *Xlo, *W0hi, *W0lo, *W1hi, *W1lo, *H0hi, *H0lo;
    float *H1;
    cudaGetSymbolAddress((void**)&Xhi,  g_Xhi);
    cudaGetSymbolAddress((void**)&Xlo,  g_Xlo);
    cudaGetSymbolAddress((void**)&W0hi, g_W0hi);
    cudaGetSymbolAddress((void**)&W0lo, g_W0lo);
    cudaGetSymbolAddress((void**)&W1hi, g_W1hi);
    cudaGetSymbolAddress((void**)&W1lo, g_W1lo);
    cudaGetSymbolAddress((void**)&H0hi, g_H0hi);
    cudaGetSymbolAddress((void**)&H0lo, g_H0lo);
    cudaGetSymbolAddress((void**)&H1,   g_H1);

    static int smem_set = 0;
    if (!smem_set) {
        cudaFuncSetAttribute(gemm_mma, cudaFuncAttributeMaxDynamicSharedMemorySize,
                             SMEM_BYTES);
        smem_set = 1;
    }

    // 0) weight transpose + fp16 split (zero-padded to [448][KP])
    {
        dim3 g1((KP1 + 31) / 32, NP_ / 32);
        transpose_split<<<g1, 256>>>(W0, W0hi, W0lo, D_, H_, KP1, NP_);
        dim3 g2((KP2 + 31) / 32, NP_ / 32);
        transpose_split<<<g2, 256>>>(W1, W1hi, W1lo, H_, H_, KP2, NP_);
    }
    // 1) gather + FM + X hi/lo
    gather_fm_kernel<<<B_, 256>>>(feats, values, weights, emb, bias);

    // 2) H0 = relu(X @ W0 + b0) -> fp16 hi/lo [16384][448] (pad cols zeroed)
    {
        dim3 grid(NP_ / TN, B_ / TM);
        gemm_mma<<<grid, 256, SMEM_BYTES>>>(Xhi, Xlo, W0hi, W0lo, b0,
                                            KP1, KP1 / BKC, 0,
                                            nullptr, H0hi, H0lo);
    }
    // 3) H1 = relu(H0 @ W1 + b1) -> fp32 [16384][400]
    {
        dim3 grid(NP_ / TN, B_ / TM);
        gemm_mma<<<grid, 256, SMEM_BYTES>>>(H0hi, H0lo, W1hi, W1lo, b1,
                                            KP2, KP2 / BKC, 1,
                                            H1, nullptr, nullptr);
    }
    // 4) out = sigmoid(ZP + relu(H1 @ W2 + b2))
    {
        const int wpb = 8;
        final_kernel<<<(B_ + wpb - 1) / wpb, wpb * 32>>>(W2, b2, out);
    }
}

// round 7
// speedup vs baseline: 1.5474x; 1.5474x over previous
#include <cuda_runtime.h>
#include <cuda_fp16.h>
#include <math.h>
#include <stdint.h>

// ---------------- problem constants ----------------
#define B_   16384
#define NF_  50
#define KE_  16
#define D_   800     // NF_*KE_
#define H_   400
#define KP1  832     // padded K for GEMM1 (26 * 32)
#define KP2  448     // padded K for GEMM2 (14 * 32)
#define NP_  448     // padded N (= 7 * 64)
#define TM   128
#define TN   64
#define BKC  32

// ---------------- scratch globals ----------------
__device__ __half g_X   [B_ * KP1];   // gathered embeddings fp16
__device__ __half g_W0t [NP_ * KP1];  // W0^T fp16 [448][832], rows>=400 zero
__device__ __half g_W1t [NP_ * KP2];  // W1^T fp16 [448][448]
__device__ __half g_H0hi[B_ * KP2];   // H0 hi (cols>=400 zeroed)
__device__ __half g_H0lo[B_ * KP2];   // H0 lo
__device__ float g_H1[B_ * H_];
__device__ float g_ZP[B_];

// ---------------- PTX helpers ----------------
__device__ __forceinline__ uint32_t smem_u32(const void* p) {
    uint32_t a;
    asm("{ .reg .u64 t; cvta.to.shared.u64 t, %1; cvt.u32.u64 %0, t; }"
        : "=r"(a) : "l"(p));
    return a;
}

#define CP16(dst, src) \
    asm volatile("cp.async.cg.shared.global [%0], [%1], 16;" \
                 :: "r"(dst), "l"(src) : "memory")
#define CP_COMMIT() asm volatile("cp.async.commit_group;" ::: "memory")
#define CP_WAIT(n)  asm volatile("cp.async.wait_group %0;" :: "n"(n) : "memory")

#define LDSM4(r, addr) \
    asm volatile("ldmatrix.sync.aligned.m8n8.x4.shared.b16 {%0,%1,%2,%3}, [%4];" \
        : "=r"((r)[0]), "=r"((r)[1]), "=r"((r)[2]), "=r"((r)[3]) : "r"(addr))

__device__ __forceinline__ void mma16f(float* c, const uint32_t* a,
                                       uint32_t b0, uint32_t b1) {
    asm volatile(
        "mma.sync.aligned.m16n8k16.row.col.f32.f16.f16.f32 "
        "{%0,%1,%2,%3}, {%4,%5,%6,%7}, {%8,%9}, {%0,%1,%2,%3};"
        : "+f"(c[0]), "+f"(c[1]), "+f"(c[2]), "+f"(c[3])
        : "r"(a[0]), "r"(a[1]), "r"(a[2]), "r"(a[3]), "r"(b0), "r"(b1));
}

__device__ __forceinline__ __half hhi(float x) { return __float2half_rn(x); }

// ---------------------------------------------------------------------------
// Kernel A: transpose  W[K][N] fp32 -> T[NP][KP] fp16 (zero pad)
// ---------------------------------------------------------------------------
__global__ __launch_bounds__(256) void transpose_h(
    const float* __restrict__ W, __half* __restrict__ T,
    int K, int N, int KP, int NP)
{
    __shared__ float t[32][33];
    const int kt = blockIdx.x * 32;
    const int nt = blockIdx.y * 32;
    const int tx = threadIdx.x & 31;
    const int ty = threadIdx.x >> 5;   // 0..7

    #pragma unroll
    for (int i = 0; i < 4; i++) {
        const int k = kt + ty + i * 8;
        float v = 0.f;
        if (k < K && nt + tx < N) v = W[(size_t)k * N + nt + tx];
        t[ty + i * 8][tx] = v;
    }
    __syncthreads();
    #pragma unroll
    for (int i = 0; i < 4; i++) {
        const int n = nt + ty + i * 8;
        const int k = kt + tx;
        if (n < NP && k < KP) T[(size_t)n * KP + k] = hhi(t[tx][ty + i * 8]);
    }
}

// ---------------------------------------------------------------------------
// Kernel B: gather + first-order + FM second-order + X fp16 materialization
// ---------------------------------------------------------------------------
__global__ __launch_bounds__(256) void gather_fm_kernel(
    const int*   __restrict__ feats,
    const float* __restrict__ values,
    const float* __restrict__ weights,
    const float* __restrict__ embedding,
    const float* __restrict__ bias)
{
    const int b   = blockIdx.x;
    const int tid = threadIdx.x;
    const int base = b * NF_;

    __shared__ float s1s[KE_];
    __shared__ float s2s[KE_];
    __shared__ float fsum;

    if (tid < KE_) { s1s[tid] = 0.f; s2s[tid] = 0.f; }
    if (tid == KE_) fsum = 0.f;
    __syncthreads();

    float a1 = 0.f, a2 = 0.f, fw = 0.f;
    const int myk = tid & 15;

    for (int i = tid; i < D_; i += 256) {
        const int f = i >> 4;
        const int feat = feats[base + f];
        const float v = values[base + f];
        const float e = embedding[(size_t)feat * KE_ + (i & 15)];
        g_X[(size_t)b * KP1 + i] = hhi(e);
        const float ev = e * v;
        a1 += ev;
        a2 += ev * ev;
        if ((i & 15) == 0) fw += weights[feat] * v;
    }
    if (tid < KP1 - D_)   // zero K padding
        g_X[(size_t)b * KP1 + D_ + tid] = __float2half(0.f);
    atomicAdd(&s1s[myk], a1);
    atomicAdd(&s2s[myk], a2);
    if ((tid & 15) == 0) atomicAdd(&fsum, fw);
    __syncthreads();

    if (tid == 0) {
        float sec = 0.f;
        #pragma unroll
        for (int k = 0; k < KE_; k++) sec += s1s[k] * s1s[k] - s2s[k];
        g_ZP[b] = fsum + bias[0] + 0.5f * sec;
    }
}

// ---------------------------------------------------------------------------
// Kernel C: fp16 tensor GEMM, SPLIT = number of A terms (1 or 2).
// D = (A [+ Alo]) @ B^T, f32 accumulate. 2-stage cp.async double buffer.
// mode 0: out = relu(D+bias) -> fp16 hi/lo at stride KP2, cols>=400 zeroed
// mode 1: out = relu(D+bias) -> fp32 at stride 400
// ---------------------------------------------------------------------------
#define ASTR 40                 // smem row stride (fp16 units)
#define A_BYTES 10240           // 128*40*2
#define B_BYTES 5120            // 64*40*2

template<int SPLIT>
__global__ __launch_bounds__(256) void gemm_fp16(
    const __half* __restrict__ Ahi, const __half* __restrict__ Alo,
    const __half* __restrict__ Bw,
    const float* __restrict__ biasp,
    int KP, int nchunks, int mode,
    float* __restrict__ outF,
    __half* __restrict__ outHi, __half* __restrict__ outLo)
{
    constexpr int OFF_AL = A_BYTES;                              // if SPLIT==2
    constexpr int OFF_B  = (SPLIT == 2) ? 2 * A_BYTES : A_BYTES;
    constexpr int STAGE_BYTES = OFF_B + B_BYTES;

    extern __shared__ char smem[];
    const uint32_t sbase = smem_u32(smem);

    const int tid  = threadIdx.x;
    const int lane = tid & 31;
    const int w    = tid >> 5;
    const int wm   = (w >> 1) << 5;   // warp M offset (0,32,64,96)
    const int wn   = (w & 1) << 5;    // warp N offset (0,32)
    const int grp  = lane >> 2;
    const int thg  = lane & 3;
    const int row0 = blockIdx.y * TM;
    const int col0 = blockIdx.x * TN;

    const int sub = lane >> 3;        // ldmatrix sub-tile select
    const int l8  = lane & 7;

    float acc[2][4][4];
    #pragma unroll
    for (int i = 0; i < 2; i++)
        #pragma unroll
        for (int j = 0; j < 4; j++)
            #pragma unroll
            for (int q = 0; q < 4; q++) acc[i][j][q] = 0.f;

    auto load_chunk = [&](int c, int s) {
        const int k0 = c * BKC;
        const uint32_t stb = sbase + s * STAGE_BYTES;
        #pragma unroll
        for (int i = 0; i < 2; i++) {
            const int v  = tid + (i << 8);
            const int r  = v >> 2;
            const int c8 = (v & 3) << 3;
            const uint32_t so = (uint32_t)(r * ASTR + c8) * 2;
            const size_t g = (size_t)(row0 + r) * KP + k0 + c8;
            CP16(stb + so, Ahi + g);
            if (SPLIT == 2) CP16(stb + OFF_AL + so, Alo + g);
        }
        {
            const int r  = tid >> 2;
            const int c8 = (tid & 3) << 3;
            const uint32_t so = (uint32_t)(r * ASTR + c8) * 2;
            const size_t g = (size_t)(col0 + r) * KP + k0 + c8;
            CP16(stb + OFF_B + so, Bw + g);
        }
        CP_COMMIT();
    };

    load_chunk(0, 0);

    for (int c = 0; c < nchunks; c++) {
        const int s = c & 1;
        if (c + 1 < nchunks) { load_chunk(c + 1, s ^ 1); CP_WAIT(1); }
        else                 { CP_WAIT(0); }
        __syncthreads();

        const uint32_t stb = sbase + s * STAGE_BYTES;
        #pragma unroll
        for (int kk = 0; kk < BKC; kk += 16) {
            uint32_t ah[2][4], al[2][4], bh[2][4];
            #pragma unroll
            for (int i = 0; i < 2; i++) {
                const int row = wm + i * 16 + ((sub & 1) << 3) + l8;
                const int kc  = kk + ((sub >> 1) << 3);
                const uint32_t ad = stb + (uint32_t)(row * ASTR + kc) * 2;
                LDSM4(ah[i], ad);
                if (SPLIT == 2) LDSM4(al[i], ad + OFF_AL);
            }
            #pragma unroll
            for (int jj = 0; jj < 2; jj++) {
                const int row = wn + jj * 16 + ((sub >> 1) << 3) + l8;
                const int kc  = kk + ((sub & 1) << 3);
                const uint32_t bd = stb + OFF_B + (uint32_t)(row * ASTR + kc) * 2;
                LDSM4(bh[jj], bd);
            }
            #pragma unroll
            for (int i = 0; i < 2; i++)
                #pragma unroll
                for (int j = 0; j < 4; j++)
                    mma16f(acc[i][j], ah[i],
                           bh[j >> 1][(j & 1) * 2], bh[j >> 1][(j & 1) * 2 + 1]);
            if (SPLIT == 2) {
                #pragma unroll
                for (int i = 0; i < 2; i++)
                    #pragma unroll
                    for (int j = 0; j < 4; j++)
                        mma16f(acc[i][j], al[i],
                               bh[j >> 1][(j & 1) * 2], bh[j >> 1][(j & 1) * 2 + 1]);
            }
        }
        __syncthreads();
    }

    // ---- epilogue: bias + relu, write straight from registers
    const float bv = *biasp;
    #pragma unroll
    for (int i = 0; i < 2; i++) {
        #pragma unroll
        for (int j = 0; j < 4; j++) {
            const int r = row0 + wm + i * 16 + grp;
            const int cc = col0 + wn + j * 8 + (thg << 1);
            #pragma unroll
            for (int half = 0; half < 2; half++) {
                const int rr = r + half * 8;
                const float x0r = fmaxf(acc[i][j][half * 2]     + bv, 0.f);
                const float x1r = fmaxf(acc[i][j][half * 2 + 1] + bv, 0.f);
                if (mode == 0) {
                    const float x0 = (cc     < H_) ? x0r : 0.f;
                    const float x1 = (cc + 1 < H_) ? x1r : 0.f;
                    const __half h0 = hhi(x0), h1 = hhi(x1);
                    __half2 hp, lp;
                    hp.x = h0; hp.y = h1;
                    lp.x = hhi(x0 - __half2float(h0));
                    lp.y = hhi(x1 - __half2float(h1));
                    const size_t o = (size_t)rr * KP2 + cc;
                    *reinterpret_cast<__half2*>(outHi + o) = hp;
                    *reinterpret_cast<__half2*>(outLo + o) = lp;
                } else {
                    if (cc < H_) {
                        float2 q; q.x = x0r; q.y = x1r;
                        *reinterpret_cast<float2*>(outF + (size_t)rr * H_ + cc) = q;
                    }
                }
            }
        }
    }
}

// ---------------------------------------------------------------------------
// Kernel D: per-sample GEMV + relu + FM partial + sigmoid
// ---------------------------------------------------------------------------
__global__ __launch_bounds__(256) void final_kernel(
    const float* __restrict__ W2,
    const float* __restrict__ b2,
    float*       __restrict__ out)
{
    const int gw   = (blockIdx.x * blockDim.x + threadIdx.x) >> 5;
    const int lane = threadIdx.x & 31;
    if (gw >= B_) return;

    float s = 0.f;
    const float* h = &g_H1[(size_t)gw * H_];
    for (int j = lane * 4; j < H_; j += 128) {
        const float4 hv = *reinterpret_cast<const float4*>(&h[j]);
        const float4 wv = *reinterpret_cast<const float4*>(&W2[j]);
        s += hv.x * wv.x + hv.y * wv.y + hv.z * wv.z + hv.w * wv.w;
    }
    #pragma unroll
    for (int o = 16; o; o >>= 1) s += __shfl_xor_sync(0xffffffffu, s, o);

    if (lane == 0) {
        const float hi = fmaxf(s + b2[0], 0.f);
        const float z  = g_ZP[gw] + hi;
        out[gw] = 1.f / (1.f + expf(-z));
    }
}

// ---------------------------------------------------------------------------
extern "C" void kernel_launch(void* const* d_in, const int* in_sizes, int n_in,
                              void* d_out, int out_size)
{
    const int*   feats   = (const int*)  d_in[1];
    const float* values  = (const float*)d_in[2];
    const float* bias    = (const float*)d_in[3];
    const float* weights = (const float*)d_in[4];
    const float* emb     = (const float*)d_in[5];
    const float* W0      = (const float*)d_in[6];
    const float* b0      = (const float*)d_in[7];
    const float* W1      = (const float*)d_in[8];
    const float* b1      = (const float*)d_in[9];
    const float* W2      = (const float*)d_in[10];
    const float* b2      = (const float*)d_in[11];
    float* out = (float*)d_out;

    __half *X, *W0t, *W1t, *H0hi, *H0lo;
    float *H1;
    cudaGetSymbolAddress((void**)&X,    g_X);
    cudaGetSymbolAddress((void**)&W0t,  g_W0t);
    cudaGetSymbolAddress((void**)&W1t,  g_W1t);
    cudaGetSymbolAddress((void**)&H0hi, g_H0hi);
    cudaGetSymbolAddress((void**)&H0lo, g_H0lo);
    cudaGetSymbolAddress((void**)&H1,   g_H1);

    const int SMEM1 = 2 * (A_BYTES + B_BYTES);              // SPLIT=1 stages
    const int SMEM2 = 2 * (2 * A_BYTES + B_BYTES);          // SPLIT=2 stages

    static int smem_set = 0;
    if (!smem_set) {
        cudaFuncSetAttribute(gemm_fp16<1>, cudaFuncAttributeMaxDynamicSharedMemorySize, SMEM1);
        cudaFuncSetAttribute(gemm_fp16<2>, cudaFuncAttributeMaxDynamicSharedMemorySize, SMEM2);
        smem_set = 1;
    }

    // 0) weight transposes -> fp16 (zero-padded)
    {
        dim3 g1((KP1 + 31) / 32, NP_ / 32);
        transpose_h<<<g1, 256>>>(W0, W0t, D_, H_, KP1, NP_);
        dim3 g2((KP2 + 31) / 32, NP_ / 32);
        transpose_h<<<g2, 256>>>(W1, W1t, H_, H_, KP2, NP_);
    }
    // 1) gather + FM + X fp16
    gather_fm_kernel<<<B_, 256>>>(feats, values, weights, emb, bias);

    // 2) H0 = relu(X @ W0 + b0) -> fp16 hi/lo [16384][448]  (1-term fp16)
    {
        dim3 grid(NP_ / TN, B_ / TM);
        gemm_fp16<1><<<grid, 256, SMEM1>>>(X, nullptr, W0t, b0,
                                           KP1, KP1 / BKC, 0,
                                           nullptr, H0hi, H0lo);
    }
    // 3) H1 = relu(H0 @ W1 + b1) -> fp32 [16384][400]  (2-term: H0 hi+lo)
    {
        dim3 grid(NP_ / TN, B_ / TM);
        gemm_fp16<2><<<grid, 256, SMEM2>>>(H0hi, H0lo, W1t, b1,
                                           KP2, KP2 / BKC, 1,
                                           H1, nullptr, nullptr);
    }
    // 4) out = sigmoid(ZP + relu(H1 @ W2 + b2))
    {
        const int wpb = 8;
        final_kernel<<<(B_ + wpb - 1) / wpb, wpb * 32>>>(W2, b2, out);
    }
}

// round 8
// speedup vs baseline: 1.7665x; 1.1416x over previous
#include <cuda_runtime.h>
#include <cuda_fp16.h>
#include <math.h>
#include <stdint.h>

// ---------------- problem constants ----------------
#define B_   16384
#define NF_  50
#define KE_  16
#define D_   800     // NF_*KE_
#define H_   400
#define KP1  832     // padded K for GEMM1 (26 * 32)
#define KP2  448     // padded K for GEMM2 (14 * 32)
#define NP_  448     // padded N (= 7 * 64)
#define TM   256
#define TN   64
#define BKC  32
#define NTHR 512

// ---------------- scratch globals ----------------
__device__ __half g_X   [B_ * KP1];   // gathered embeddings fp16
__device__ __half g_W0t [NP_ * KP1];  // W0^T fp16 [448][832], rows>=400 zero
__device__ __half g_W1t [NP_ * KP2];  // W1^T fp16 [448][448]
__device__ __half g_H0c [B_ * KP2];   // centered H0 (H0 - b0plus), fp16
__device__ float g_cs1[NP_];          // colsum of W1 (pad 0)
__device__ float g_S  [B_];           // fused GEMV accumulator
__device__ float g_ZP [B_];           // first + second (+bias)

// ---------------- PTX helpers ----------------
__device__ __forceinline__ uint32_t smem_u32(const void* p) {
    uint32_t a;
    asm("{ .reg .u64 t; cvta.to.shared.u64 t, %1; cvt.u32.u64 %0, t; }"
        : "=r"(a) : "l"(p));
    return a;
}

#define CP16(dst, src) \
    asm volatile("cp.async.cg.shared.global [%0], [%1], 16;" \
                 :: "r"(dst), "l"(src) : "memory")
#define CP_COMMIT() asm volatile("cp.async.commit_group;" ::: "memory")
#define CP_WAIT(n)  asm volatile("cp.async.wait_group %0;" :: "n"(n) : "memory")

#define LDSM4(r, addr) \
    asm volatile("ldmatrix.sync.aligned.m8n8.x4.shared.b16 {%0,%1,%2,%3}, [%4];" \
        : "=r"((r)[0]), "=r"((r)[1]), "=r"((r)[2]), "=r"((r)[3]) : "r"(addr))

__device__ __forceinline__ void mma16f(float* c, const uint32_t* a,
                                       uint32_t b0, uint32_t b1) {
    asm volatile(
        "mma.sync.aligned.m16n8k16.row.col.f32.f16.f16.f32 "
        "{%0,%1,%2,%3}, {%4,%5,%6,%7}, {%8,%9}, {%0,%1,%2,%3};"
        : "+f"(c[0]), "+f"(c[1]), "+f"(c[2]), "+f"(c[3])
        : "r"(a[0]), "r"(a[1]), "r"(a[2]), "r"(a[3]), "r"(b0), "r"(b1));
}

__device__ __forceinline__ __half hhi(float x) { return __float2half_rn(x); }

// ---------------------------------------------------------------------------
// Kernel A: transpose  W[K][N] fp32 -> T[NP][KP] fp16 (zero pad)
// ---------------------------------------------------------------------------
__global__ __launch_bounds__(256) void transpose_h(
    const float* __restrict__ W, __half* __restrict__ T,
    int K, int N, int KP, int NP)
{
    __shared__ float t[32][33];
    const int kt = blockIdx.x * 32;
    const int nt = blockIdx.y * 32;
    const int tx = threadIdx.x & 31;
    const int ty = threadIdx.x >> 5;

    #pragma unroll
    for (int i = 0; i < 4; i++) {
        const int k = kt + ty + i * 8;
        float v = 0.f;
        if (k < K && nt + tx < N) v = W[(size_t)k * N + nt + tx];
        t[ty + i * 8][tx] = v;
    }
    __syncthreads();
    #pragma unroll
    for (int i = 0; i < 4; i++) {
        const int n = nt + ty + i * 8;
        const int k = kt + tx;
        if (n < NP && k < KP) T[(size_t)n * KP + k] = hhi(t[tx][ty + i * 8]);
    }
}

// ---------------------------------------------------------------------------
// Kernel A2: column sums of W1 [400][400] -> cs1[448] (pad 0)
// ---------------------------------------------------------------------------
__global__ __launch_bounds__(128) void colsum_kernel(const float* __restrict__ W1)
{
    const int n = blockIdx.x * 128 + threadIdx.x;
    if (n >= NP_) return;
    float s = 0.f;
    if (n < H_)
        for (int k = 0; k < H_; k++) s += W1[(size_t)k * H_ + n];
    g_cs1[n] = s;
}

// ---------------------------------------------------------------------------
// Kernel B: gather + first-order + FM second-order + X fp16; zero g_S
// ---------------------------------------------------------------------------
__global__ __launch_bounds__(256) void gather_fm_kernel(
    const int*   __restrict__ feats,
    const float* __restrict__ values,
    const float* __restrict__ weights,
    const float* __restrict__ embedding,
    const float* __restrict__ bias)
{
    const int b   = blockIdx.x;
    const int tid = threadIdx.x;
    const int base = b * NF_;

    __shared__ float s1s[KE_];
    __shared__ float s2s[KE_];
    __shared__ float fsum;

    if (tid < KE_) { s1s[tid] = 0.f; s2s[tid] = 0.f; }
    if (tid == KE_) fsum = 0.f;
    __syncthreads();

    float a1 = 0.f, a2 = 0.f, fw = 0.f;
    const int myk = tid & 15;

    for (int i = tid; i < D_; i += 256) {
        const int f = i >> 4;
        const int feat = feats[base + f];
        const float v = values[base + f];
        const float e = embedding[(size_t)feat * KE_ + (i & 15)];
        g_X[(size_t)b * KP1 + i] = hhi(e);
        const float ev = e * v;
        a1 += ev;
        a2 += ev * ev;
        if ((i & 15) == 0) fw += weights[feat] * v;
    }
    if (tid < KP1 - D_)   // zero K padding
        g_X[(size_t)b * KP1 + D_ + tid] = __float2half(0.f);
    atomicAdd(&s1s[myk], a1);
    atomicAdd(&s2s[myk], a2);
    if ((tid & 15) == 0) atomicAdd(&fsum, fw);
    __syncthreads();

    if (tid == 0) {
        float sec = 0.f;
        #pragma unroll
        for (int k = 0; k < KE_; k++) sec += s1s[k] * s1s[k] - s2s[k];
        g_ZP[b] = fsum + bias[0] + 0.5f * sec;
        g_S[b]  = 0.f;
    }
}

// ---------------------------------------------------------------------------
// Kernel C: single-term fp16 tensor GEMM, CTA 256x64, 512 thr (16 warps 8Mx2N,
// warp tile 32x32), BK=32, 2-stage cp.async double buffer, f32 accumulate.
// mode 0 (GEMM1): x=relu(acc+b0); store fp16(x - max(b0,0)) -> H0c stride KP2
// mode 1 (GEMM2): x=relu(acc + b0p*cs1[c] + b1); atomicAdd rowsum(x*W2) -> g_S
// ---------------------------------------------------------------------------
#define ASTR 40                 // smem row stride (fp16 units)
#define A_BYTES 20480           // 256*40*2
#define B_BYTES 5120            // 64*40*2
#define STAGE_BYTES (A_BYTES + B_BYTES)
#define SMEM_BYTES (2 * STAGE_BYTES)

__global__ __launch_bounds__(NTHR) void gemm_fp16(
    const __half* __restrict__ A,
    const __half* __restrict__ Bw,
    const float* __restrict__ biasp,    // own layer bias (b0 or b1)
    const float* __restrict__ prevbp,   // previous layer bias (b0) for mode 1
    const float* __restrict__ W2,       // mode 1 only
    int KP, int nchunks, int mode,
    __half* __restrict__ outH)          // mode 0 only
{
    extern __shared__ char smem[];
    const uint32_t sbase = smem_u32(smem);

    const int tid  = threadIdx.x;
    const int lane = tid & 31;
    const int w    = tid >> 5;
    const int wm   = (w >> 1) << 5;   // warp M offset (0..224)
    const int wn   = (w & 1) << 5;    // warp N offset (0,32)
    const int grp  = lane >> 2;
    const int thg  = lane & 3;
    const int row0 = blockIdx.y * TM;
    const int col0 = blockIdx.x * TN;

    const int sub = lane >> 3;
    const int l8  = lane & 7;

    float acc[2][4][4];
    #pragma unroll
    for (int i = 0; i < 2; i++)
        #pragma unroll
        for (int j = 0; j < 4; j++)
            #pragma unroll
            for (int q = 0; q < 4; q++) acc[i][j][q] = 0.f;

    auto load_chunk = [&](int c, int s) {
        const int k0 = c * BKC;
        const uint32_t stb = sbase + s * STAGE_BYTES;
        #pragma unroll
        for (int i = 0; i < 2; i++) {
            const int v  = tid + (i << 9);          // 1024 vectors over 512 thr
            const int r  = v >> 2;
            const int c8 = (v & 3) << 3;
            const uint32_t so = (uint32_t)(r * ASTR + c8) * 2;
            CP16(stb + so, A + (size_t)(row0 + r) * KP + k0 + c8);
        }
        if (tid < 256) {
            const int r  = tid >> 2;
            const int c8 = (tid & 3) << 3;
            const uint32_t so = (uint32_t)(r * ASTR + c8) * 2;
            CP16(stb + A_BYTES + so, Bw + (size_t)(col0 + r) * KP + k0 + c8);
        }
        CP_COMMIT();
    };

    load_chunk(0, 0);

    for (int c = 0; c < nchunks; c++) {
        const int s = c & 1;
        if (c + 1 < nchunks) { load_chunk(c + 1, s ^ 1); CP_WAIT(1); }
        else                 { CP_WAIT(0); }
        __syncthreads();

        const uint32_t stb = sbase + s * STAGE_BYTES;
        #pragma unroll
        for (int kk = 0; kk < BKC; kk += 16) {
            uint32_t ah[2][4], bh[2][4];
            #pragma unroll
            for (int i = 0; i < 2; i++) {
                const int row = wm + i * 16 + ((sub & 1) << 3) + l8;
                const int kc  = kk + ((sub >> 1) << 3);
                LDSM4(ah[i], stb + (uint32_t)(row * ASTR + kc) * 2);
            }
            #pragma unroll
            for (int jj = 0; jj < 2; jj++) {
                const int row = wn + jj * 16 + ((sub >> 1) << 3) + l8;
                const int kc  = kk + ((sub & 1) << 3);
                LDSM4(bh[jj], stb + A_BYTES + (uint32_t)(row * ASTR + kc) * 2);
            }
            #pragma unroll
            for (int i = 0; i < 2; i++)
                #pragma unroll
                for (int j = 0; j < 4; j++)
                    mma16f(acc[i][j], ah[i],
                           bh[j >> 1][(j & 1) * 2], bh[j >> 1][(j & 1) * 2 + 1]);
        }
        __syncthreads();
    }

    const float bv  = *biasp;
    if (mode == 0) {
        // H0c = relu(acc + b0) - max(b0, 0), fp16, stride KP2
        const float bp = fmaxf(bv, 0.f);
        #pragma unroll
        for (int i = 0; i < 2; i++) {
            #pragma unroll
            for (int j = 0; j < 4; j++) {
                const int r = row0 + wm + i * 16 + grp;
                const int cc = col0 + wn + j * 8 + (thg << 1);
                #pragma unroll
                for (int half = 0; half < 2; half++) {
                    const int rr = r + half * 8;
                    const float x0 = fmaxf(acc[i][j][half * 2]     + bv, 0.f) - bp;
                    const float x1 = fmaxf(acc[i][j][half * 2 + 1] + bv, 0.f) - bp;
                    __half2 hp; hp.x = hhi(x0); hp.y = hhi(x1);
                    *reinterpret_cast<__half2*>(outH + (size_t)rr * KP2 + cc) = hp;
                }
            }
        }
    } else {
        // H1 = relu(acc + b0p*cs1[c] + b1); rowsum(H1 * W2) -> atomicAdd(g_S)
        const float bp = fmaxf(*prevbp, 0.f);
        float rs[2][2] = {{0.f, 0.f}, {0.f, 0.f}};
        #pragma unroll
        for (int i = 0; i < 2; i++) {
            #pragma unroll
            for (int j = 0; j < 4; j++) {
                const int cc = col0 + wn + j * 8 + (thg << 1);
                const float w2a = (cc     < H_) ? W2[cc]     : 0.f;
                const float w2b = (cc + 1 < H_) ? W2[cc + 1] : 0.f;
                const float ca = g_cs1[cc];
                const float cb = g_cs1[cc + 1];
                #pragma unroll
                for (int half = 0; half < 2; half++) {
                    const float x0 = fmaxf(acc[i][j][half * 2]     + bp * ca + bv, 0.f);
                    const float x1 = fmaxf(acc[i][j][half * 2 + 1] + bp * cb + bv, 0.f);
                    rs[i][half] += x0 * w2a + x1 * w2b;
                }
            }
        }
        #pragma unroll
        for (int i = 0; i < 2; i++)
            #pragma unroll
            for (int half = 0; half < 2; half++) {
                float v = rs[i][half];
                v += __shfl_xor_sync(0xffffffffu, v, 1);
                v += __shfl_xor_sync(0xffffffffu, v, 2);
                if (thg == 0) {
                    const int rr = row0 + wm + i * 16 + grp + half * 8;
                    atomicAdd(&g_S[rr], v);
                }
            }
    }
}

// ---------------------------------------------------------------------------
// Kernel D: out = sigmoid(ZP + relu(S + b2))
// ---------------------------------------------------------------------------
__global__ __launch_bounds__(256) void final_small(
    const float* __restrict__ b2, float* __restrict__ out)
{
    const int b = blockIdx.x * 256 + threadIdx.x;
    if (b >= B_) return;
    const float hi = fmaxf(g_S[b] + b2[0], 0.f);
    const float z  = g_ZP[b] + hi;
    out[b] = 1.f / (1.f + expf(-z));
}

// ---------------------------------------------------------------------------
extern "C" void kernel_launch(void* const* d_in, const int* in_sizes, int n_in,
                              void* d_out, int out_size)
{
    const int*   feats   = (const int*)  d_in[1];
    const float* values  = (const float*)d_in[2];
    const float* bias    = (const float*)d_in[3];
    const float* weights = (const float*)d_in[4];
    const float* emb     = (const float*)d_in[5];
    const float* W0      = (const float*)d_in[6];
    const float* b0      = (const float*)d_in[7];
    const float* W1      = (const float*)d_in[8];
    const float* b1      = (const float*)d_in[9];
    const float* W2      = (const float*)d_in[10];
    const float* b2      = (const float*)d_in[11];
    float* out = (float*)d_out;

    __half *X, *W0t, *W1t, *H0c;
    cudaGetSymbolAddress((void**)&X,    g_X);
    cudaGetSymbolAddress((void**)&W0t,  g_W0t);
    cudaGetSymbolAddress((void**)&W1t,  g_W1t);
    cudaGetSymbolAddress((void**)&H0c,  g_H0c);

    static int smem_set = 0;
    if (!smem_set) {
        cudaFuncSetAttribute(gemm_fp16, cudaFuncAttributeMaxDynamicSharedMemorySize,
                             SMEM_BYTES);
        smem_set = 1;
    }

    // 0) weight transposes + W1 column sums
    {
        dim3 g1((KP1 + 31) / 32, NP_ / 32);
        transpose_h<<<g1, 256>>>(W0, W0t, D_, H_, KP1, NP_);
        dim3 g2((KP2 + 31) / 32, NP_ / 32);
        transpose_h<<<g2, 256>>>(W1, W1t, H_, H_, KP2, NP_);
        colsum_kernel<<<(NP_ + 127) / 128, 128>>>(W1);
    }
    // 1) gather + FM + X fp16 (+ zero g_S)
    gather_fm_kernel<<<B_, 256>>>(feats, values, weights, emb, bias);

    // 2) H0c = relu(X @ W0 + b0) - b0p  -> fp16 [16384][448]
    {
        dim3 grid(NP_ / TN, B_ / TM);
        gemm_fp16<<<grid, NTHR, SMEM_BYTES>>>(X, W0t, b0, nullptr, nullptr,
                                              KP1, KP1 / BKC, 0, H0c);
    }
    // 3) g_S += rowsum(relu(H0c @ W1 + b0p*cs1 + b1) * W2)  (fused GEMV)
    {
        dim3 grid(NP_ / TN, B_ / TM);
        gemm_fp16<<<grid, NTHR, SMEM_BYTES>>>(H0c, W1t, b1, b0, W2,
                                              KP2, KP2 / BKC, 1, nullptr);
    }
    // 4) out = sigmoid(ZP + relu(S + b2))
    final_small<<<(B_ + 255) / 256, 256>>>(b2, out);
}

// round 9
// speedup vs baseline: 2.3782x; 1.3463x over previous
#include <cuda_runtime.h>
#include <cuda_fp16.h>
#include <math.h>
#include <stdint.h>

// ---------------- problem constants ----------------
#define B_   16384
#define NF_  50
#define KE_  16
#define D_   800     // NF_*KE_
#define H_   400
#define KP1  832     // padded K for GEMM1 (26 * 32)
#define KP2  448     // padded K for GEMM2 (14 * 32)
#define NP_  448     // padded N (= 7 * 64)
#define TM   256
#define TN   64
#define BKC  32
#define NTHR 512

// ---------------- scratch globals ----------------
__device__ __half g_X   [B_ * KP1];   // gathered embeddings fp16
__device__ __half g_W0t [NP_ * KP1];  // W0^T fp16 [448][832], rows>=400 zero
__device__ __half g_W1t [NP_ * KP2];  // W1^T fp16 [448][448]
__device__ __half g_H0c [B_ * KP2];   // centered H0 (H0 - b0plus), fp16
__device__ float g_cs1[NP_];          // colsum of W1 (pad 0)
__device__ float g_S  [B_];           // fused GEMV accumulator
__device__ float g_ZP [B_];           // first + second (+bias)

// ---------------- PTX helpers ----------------
__device__ __forceinline__ uint32_t smem_u32(const void* p) {
    uint32_t a;
    asm("{ .reg .u64 t; cvta.to.shared.u64 t, %1; cvt.u32.u64 %0, t; }"
        : "=r"(a) : "l"(p));
    return a;
}

#define CP16(dst, src) \
    asm volatile("cp.async.cg.shared.global [%0], [%1], 16;" \
                 :: "r"(dst), "l"(src) : "memory")
#define CP_COMMIT() asm volatile("cp.async.commit_group;" ::: "memory")
#define CP_WAIT(n)  asm volatile("cp.async.wait_group %0;" :: "n"(n) : "memory")

#define LDSM4(r, addr) \
    asm volatile("ldmatrix.sync.aligned.m8n8.x4.shared.b16 {%0,%1,%2,%3}, [%4];" \
        : "=r"((r)[0]), "=r"((r)[1]), "=r"((r)[2]), "=r"((r)[3]) : "r"(addr))

__device__ __forceinline__ void mma16f(float* c, const uint32_t* a,
                                       uint32_t b0, uint32_t b1) {
    asm volatile(
        "mma.sync.aligned.m16n8k16.row.col.f32.f16.f16.f32 "
        "{%0,%1,%2,%3}, {%4,%5,%6,%7}, {%8,%9}, {%0,%1,%2,%3};"
        : "+f"(c[0]), "+f"(c[1]), "+f"(c[2]), "+f"(c[3])
        : "r"(a[0]), "r"(a[1]), "r"(a[2]), "r"(a[3]), "r"(b0), "r"(b1));
}

__device__ __forceinline__ __half hhi(float x) { return __float2half_rn(x); }

// ---------------------------------------------------------------------------
// Kernel A: transpose  W[K][N] fp32 -> T[NP][KP] fp16 (zero pad)
// ---------------------------------------------------------------------------
__global__ __launch_bounds__(256) void transpose_h(
    const float* __restrict__ W, __half* __restrict__ T,
    int K, int N, int KP, int NP)
{
    __shared__ float t[32][33];
    const int kt = blockIdx.x * 32;
    const int nt = blockIdx.y * 32;
    const int tx = threadIdx.x & 31;
    const int ty = threadIdx.x >> 5;

    #pragma unroll
    for (int i = 0; i < 4; i++) {
        const int k = kt + ty + i * 8;
        float v = 0.f;
        if (k < K && nt + tx < N) v = W[(size_t)k * N + nt + tx];
        t[ty + i * 8][tx] = v;
    }
    __syncthreads();
    #pragma unroll
    for (int i = 0; i < 4; i++) {
        const int n = nt + ty + i * 8;
        const int k = kt + tx;
        if (n < NP && k < KP) T[(size_t)n * KP + k] = hhi(t[tx][ty + i * 8]);
    }
}

// ---------------------------------------------------------------------------
// Kernel A2a: zero cs1; A2b: coalesced column sums of W1 via 8-block atomics
// ---------------------------------------------------------------------------
__global__ void zero_cs1() { if (threadIdx.x < NP_) g_cs1[threadIdx.x] = 0.f; }

__global__ __launch_bounds__(512) void colsum_kernel(const float* __restrict__ W1)
{
    const int n = threadIdx.x;
    if (n >= H_) return;
    const int r0 = blockIdx.x * 50;
    float s = 0.f;
    for (int r = r0; r < r0 + 50; r++) s += W1[(size_t)r * H_ + n];
    atomicAdd(&g_cs1[n], s);
}

// ---------------------------------------------------------------------------
// Kernel B: gather + FM, warp-per-sample, float4 vectorized, shfl reductions.
// 8 warps/block, grid = B_/8. Lane owns k-slice k=(lane&3)*4+q.
// ---------------------------------------------------------------------------
__global__ __launch_bounds__(256) void gather_fm_kernel(
    const int*   __restrict__ feats,
    const float* __restrict__ values,
    const float* __restrict__ weights,
    const float* __restrict__ embedding,
    const float* __restrict__ bias)
{
    const int wid  = threadIdx.x >> 5;
    const int lane = threadIdx.x & 31;
    const int b    = blockIdx.x * 8 + wid;
    const int base = b * NF_;

    // ---- first order: lane covers f=lane and f=lane+32
    float fw = weights[feats[base + lane]] * values[base + lane];
    if (lane < NF_ - 32)
        fw += weights[feats[base + 32 + lane]] * values[base + 32 + lane];

    // ---- main sweep: 200 float4s (50 features x 4 quads)
    float a1[4] = {0.f, 0.f, 0.f, 0.f};
    float a2[4] = {0.f, 0.f, 0.f, 0.f};

    __half* xrow = g_X + (size_t)b * KP1;

    #pragma unroll
    for (int j = 0; j < 7; j++) {
        const int i4 = j * 32 + lane;
        if (j < 6 || lane < 8) {
            const int f  = i4 >> 2;
            const int k4 = (i4 & 3) << 2;
            const int feat = feats[base + f];
            const float v  = values[base + f];
            const float4 e = *reinterpret_cast<const float4*>(
                embedding + (size_t)feat * KE_ + k4);
            __half2 h01, h23;
            h01.x = hhi(e.x); h01.y = hhi(e.y);
            h23.x = hhi(e.z); h23.y = hhi(e.w);
            uint2 pk;
            pk.x = *reinterpret_cast<uint32_t*>(&h01);
            pk.y = *reinterpret_cast<uint32_t*>(&h23);
            *reinterpret_cast<uint2*>(xrow + i4 * 4) = pk;
            const float e0 = e.x * v, e1 = e.y * v, e2 = e.z * v, e3 = e.w * v;
            a1[0] += e0; a2[0] += e0 * e0;
            a1[1] += e1; a2[1] += e1 * e1;
            a1[2] += e2; a2[2] += e2 * e2;
            a1[3] += e3; a2[3] += e3 * e3;
        }
    }
    // zero K padding: elements 800..831 (lanes 0..7 write 8B each)
    if (lane < 8) {
        uint2 z; z.x = 0u; z.y = 0u;
        *reinterpret_cast<uint2*>(xrow + 800 + lane * 4) = z;
    }

    // ---- reduce a1/a2 across the 8 lanes sharing (lane&3)
    #pragma unroll
    for (int o = 4; o <= 16; o <<= 1) {
        #pragma unroll
        for (int q = 0; q < 4; q++) {
            a1[q] += __shfl_xor_sync(0xffffffffu, a1[q], o);
            a2[q] += __shfl_xor_sync(0xffffffffu, a2[q], o);
        }
    }
    // per-lane partial second-order over its 4 k's, then combine 4 groups
    float sec = 0.f;
    #pragma unroll
    for (int q = 0; q < 4; q++) sec += a1[q] * a1[q] - a2[q];
    sec += __shfl_xor_sync(0xffffffffu, sec, 1);
    sec += __shfl_xor_sync(0xffffffffu, sec, 2);

    // ---- reduce first order over full warp
    #pragma unroll
    for (int o = 1; o <= 16; o <<= 1) fw += __shfl_xor_sync(0xffffffffu, fw, o);

    if (lane == 0) {
        g_ZP[b] = fw + bias[0] + 0.5f * sec;
        g_S[b]  = 0.f;
    }
}

// ---------------------------------------------------------------------------
// Kernel C: single-term fp16 tensor GEMM, CTA 256x64, 512 thr (16 warps 8Mx2N,
// warp tile 32x32), BK=32, 2-stage cp.async double buffer, f32 accumulate.
// mode 0 (GEMM1): x=relu(acc+b0); store fp16(x - max(b0,0)) -> H0c stride KP2
// mode 1 (GEMM2): x=relu(acc + b0p*cs1[c] + b1); atomicAdd rowsum(x*W2) -> g_S
// ---------------------------------------------------------------------------
#define ASTR 40                 // smem row stride (fp16 units)
#define A_BYTES 20480           // 256*40*2
#define B_BYTES 5120            // 64*40*2
#define STAGE_BYTES (A_BYTES + B_BYTES)
#define SMEM_BYTES (2 * STAGE_BYTES)

__global__ __launch_bounds__(NTHR) void gemm_fp16(
    const __half* __restrict__ A,
    const __half* __restrict__ Bw,
    const float* __restrict__ biasp,    // own layer bias (b0 or b1)
    const float* __restrict__ prevbp,   // previous layer bias (b0) for mode 1
    const float* __restrict__ W2,       // mode 1 only
    int KP, int nchunks, int mode,
    __half* __restrict__ outH)          // mode 0 only
{
    extern __shared__ char smem[];
    const uint32_t sbase = smem_u32(smem);

    const int tid  = threadIdx.x;
    const int lane = tid & 31;
    const int w    = tid >> 5;
    const int wm   = (w >> 1) << 5;   // warp M offset (0..224)
    const int wn   = (w & 1) << 5;    // warp N offset (0,32)
    const int grp  = lane >> 2;
    const int thg  = lane & 3;
    const int row0 = blockIdx.y * TM;
    const int col0 = blockIdx.x * TN;

    const int sub = lane >> 3;
    const int l8  = lane & 7;

    float acc[2][4][4];
    #pragma unroll
    for (int i = 0; i < 2; i++)
        #pragma unroll
        for (int j = 0; j < 4; j++)
            #pragma unroll
            for (int q = 0; q < 4; q++) acc[i][j][q] = 0.f;

    auto load_chunk = [&](int c, int s) {
        const int k0 = c * BKC;
        const uint32_t stb = sbase + s * STAGE_BYTES;
        #pragma unroll
        for (int i = 0; i < 2; i++) {
            const int v  = tid + (i << 9);          // 1024 vectors over 512 thr
            const int r  = v >> 2;
            const int c8 = (v & 3) << 3;
            const uint32_t so = (uint32_t)(r * ASTR + c8) * 2;
            CP16(stb + so, A + (size_t)(row0 + r) * KP + k0 + c8);
        }
        if (tid < 256) {
            const int r  = tid >> 2;
            const int c8 = (tid & 3) << 3;
            const uint32_t so = (uint32_t)(r * ASTR + c8) * 2;
            CP16(stb + A_BYTES + so, Bw + (size_t)(col0 + r) * KP + k0 + c8);
        }
        CP_COMMIT();
    };

    load_chunk(0, 0);

    for (int c = 0; c < nchunks; c++) {
        const int s = c & 1;
        if (c + 1 < nchunks) { load_chunk(c + 1, s ^ 1); CP_WAIT(1); }
        else                 { CP_WAIT(0); }
        __syncthreads();

        const uint32_t stb = sbase + s * STAGE_BYTES;
        #pragma unroll
        for (int kk = 0; kk < BKC; kk += 16) {
            uint32_t ah[2][4], bh[2][4];
            #pragma unroll
            for (int i = 0; i < 2; i++) {
                const int row = wm + i * 16 + ((sub & 1) << 3) + l8;
                const int kc  = kk + ((sub >> 1) << 3);
                LDSM4(ah[i], stb + (uint32_t)(row * ASTR + kc) * 2);
            }
            #pragma unroll
            for (int jj = 0; jj < 2; jj++) {
                const int row = wn + jj * 16 + ((sub >> 1) << 3) + l8;
                const int kc  = kk + ((sub & 1) << 3);
                LDSM4(bh[jj], stb + A_BYTES + (uint32_t)(row * ASTR + kc) * 2);
            }
            #pragma unroll
            for (int i = 0; i < 2; i++)
                #pragma unroll
                for (int j = 0; j < 4; j++)
                    mma16f(acc[i][j], ah[i],
                           bh[j >> 1][(j & 1) * 2], bh[j >> 1][(j & 1) * 2 + 1]);
        }
        __syncthreads();
    }

    const float bv  = *biasp;
    if (mode == 0) {
        // H0c = relu(acc + b0) - max(b0, 0), fp16, stride KP2
        const float bp = fmaxf(bv, 0.f);
        #pragma unroll
        for (int i = 0; i < 2; i++) {
            #pragma unroll
            for (int j = 0; j < 4; j++) {
                const int r = row0 + wm + i * 16 + grp;
                const int cc = col0 + wn + j * 8 + (thg << 1);
                #pragma unroll
                for (int half = 0; half < 2; half++) {
                    const int rr = r + half * 8;
                    const float x0 = fmaxf(acc[i][j][half * 2]     + bv, 0.f) - bp;
                    const float x1 = fmaxf(acc[i][j][half * 2 + 1] + bv, 0.f) - bp;
                    __half2 hp; hp.x = hhi(x0); hp.y = hhi(x1);
                    *reinterpret_cast<__half2*>(outH + (size_t)rr * KP2 + cc) = hp;
                }
            }
        }
    } else {
        // H1 = relu(acc + b0p*cs1[c] + b1); rowsum(H1 * W2) -> atomicAdd(g_S)
        const float bp = fmaxf(*prevbp, 0.f);
        float rs[2][2] = {{0.f, 0.f}, {0.f, 0.f}};
        #pragma unroll
        for (int i = 0; i < 2; i++) {
            #pragma unroll
            for (int j = 0; j < 4; j++) {
                const int cc = col0 + wn + j * 8 + (thg << 1);
                const float w2a = (cc     < H_) ? W2[cc]     : 0.f;
                const float w2b = (cc + 1 < H_) ? W2[cc + 1] : 0.f;
                const float ca = g_cs1[cc];
                const float cb = g_cs1[cc + 1];
                #pragma unroll
                for (int half = 0; half < 2; half++) {
                    const float x0 = fmaxf(acc[i][j][half * 2]     + bp * ca + bv, 0.f);
                    const float x1 = fmaxf(acc[i][j][half * 2 + 1] + bp * cb + bv, 0.f);
                    rs[i][half] += x0 * w2a + x1 * w2b;
                }
            }
        }
        #pragma unroll
        for (int i = 0; i < 2; i++)
            #pragma unroll
            for (int half = 0; half < 2; half++) {
                float v = rs[i][half];
                v += __shfl_xor_sync(0xffffffffu, v, 1);
                v += __shfl_xor_sync(0xffffffffu, v, 2);
                if (thg == 0) {
                    const int rr = row0 + wm + i * 16 + grp + half * 8;
                    atomicAdd(&g_S[rr], v);
                }
            }
    }
}

// ---------------------------------------------------------------------------
// Kernel D: out = sigmoid(ZP + relu(S + b2))
// ---------------------------------------------------------------------------
__global__ __launch_bounds__(256) void final_small(
    const float* __restrict__ b2, float* __restrict__ out)
{
    const int b = blockIdx.x * 256 + threadIdx.x;
    if (b >= B_) return;
    const float hi = fmaxf(g_S[b] + b2[0], 0.f);
    const float z  = g_ZP[b] + hi;
    out[b] = 1.f / (1.f + expf(-z));
}

// ---------------------------------------------------------------------------
extern "C" void kernel_launch(void* const* d_in, const int* in_sizes, int n_in,
                              void* d_out, int out_size)
{
    const int*   feats   = (const int*)  d_in[1];
    const float* values  = (const float*)d_in[2];
    const float* bias    = (const float*)d_in[3];
    const float* weights = (const float*)d_in[4];
    const float* emb     = (const float*)d_in[5];
    const float* W0      = (const float*)d_in[6];
    const float* b0      = (const float*)d_in[7];
    const float* W1      = (const float*)d_in[8];
    const float* b1      = (const float*)d_in[9];
    const float* W2      = (const float*)d_in[10];
    const float* b2      = (const float*)d_in[11];
    float* out = (float*)d_out;

    __half *X, *W0t, *W1t, *H0c;
    cudaGetSymbolAddress((void**)&X,    g_X);
    cudaGetSymbolAddress((void**)&W0t,  g_W0t);
    cudaGetSymbolAddress((void**)&W1t,  g_W1t);
    cudaGetSymbolAddress((void**)&H0c,  g_H0c);

    static int smem_set = 0;
    if (!smem_set) {
        cudaFuncSetAttribute(gemm_fp16, cudaFuncAttributeMaxDynamicSharedMemorySize,
                             SMEM_BYTES);
        smem_set = 1;
    }

    // 0) weight transposes + W1 column sums (coalesced, 8-block atomic)
    {
        zero_cs1<<<1, NP_>>>();
        dim3 g1((KP1 + 31) / 32, NP_ / 32);
        transpose_h<<<g1, 256>>>(W0, W0t, D_, H_, KP1, NP_);
        dim3 g2((KP2 + 31) / 32, NP_ / 32);
        transpose_h<<<g2, 256>>>(W1, W1t, H_, H_, KP2, NP_);
        colsum_kernel<<<8, 512>>>(W1);
    }
    // 1) gather + FM + X fp16 (+ zero g_S): warp per sample
    gather_fm_kernel<<<B_ / 8, 256>>>(feats, values, weights, emb, bias);

    // 2) H0c = relu(X @ W0 + b0) - b0p  -> fp16 [16384][448]
    {
        dim3 grid(NP_ / TN, B_ / TM);
        gemm_fp16<<<grid, NTHR, SMEM_BYTES>>>(X, W0t, b0, nullptr, nullptr,
                                              KP1, KP1 / BKC, 0, H0c);
    }
    // 3) g_S += rowsum(relu(H0c @ W1 + b0p*cs1 + b1) * W2)  (fused GEMV)
    {
        dim3 grid(NP_ / TN, B_ / TM);
        gemm_fp16<<<grid, NTHR, SMEM_BYTES>>>(H0c, W1t, b1, b0, W2,
                                              KP2, KP2 / BKC, 1, nullptr);
    }
    // 4) out = sigmoid(ZP + relu(S + b2))
    final_small<<<(B_ + 255) / 256, 256>>>(b2, out);
}

// round 10
// speedup vs baseline: 2.5081x; 1.0546x over previous
#include <cuda_runtime.h>
#include <cuda_fp16.h>
#include <math.h>
#include <stdint.h>

// ---------------- problem constants ----------------
#define B_   16384
#define NF_  50
#define KE_  16
#define D_   800     // NF_*KE_
#define H_   400
#define KP1  800     // K for GEMM1 (25 * 32, exact)
#define KP2  448     // padded K for GEMM2 (14 * 32)
#define NP_  448     // padded N (= 7 * 64)
#define TM   256
#define TN   64
#define BKC  32
#define NTHR 512

// ---------------- scratch globals ----------------
__device__ __half g_X   [B_ * KP1];   // gathered embeddings fp16
__device__ __half g_W0t [NP_ * KP1];  // W0^T fp16 [448][800], rows>=400 zero
__device__ __half g_W1t [NP_ * KP2];  // W1^T fp16 [448][448]
__device__ __half g_H0c [B_ * KP2];   // centered H0 (H0 - b0plus), fp16
__device__ float g_cs1[NP_];          // colsum of W1 (cols >=400 unused)
__device__ float g_S  [B_];           // fused GEMV accumulator
__device__ float g_ZP [B_];           // first + second (+bias)

// ---------------- PTX helpers ----------------
__device__ __forceinline__ uint32_t smem_u32(const void* p) {
    uint32_t a;
    asm("{ .reg .u64 t; cvta.to.shared.u64 t, %1; cvt.u32.u64 %0, t; }"
        : "=r"(a) : "l"(p));
    return a;
}

#define CP16(dst, src) \
    asm volatile("cp.async.cg.shared.global [%0], [%1], 16;" \
                 :: "r"(dst), "l"(src) : "memory")
#define CP_COMMIT() asm volatile("cp.async.commit_group;" ::: "memory")
#define CP_WAIT(n)  asm volatile("cp.async.wait_group %0;" :: "n"(n) : "memory")

#define LDSM4(r, addr) \
    asm volatile("ldmatrix.sync.aligned.m8n8.x4.shared.b16 {%0,%1,%2,%3}, [%4];" \
        : "=r"((r)[0]), "=r"((r)[1]), "=r"((r)[2]), "=r"((r)[3]) : "r"(addr))

__device__ __forceinline__ void mma16f(float* c, const uint32_t* a,
                                       uint32_t b0, uint32_t b1) {
    asm volatile(
        "mma.sync.aligned.m16n8k16.row.col.f32.f16.f16.f32 "
        "{%0,%1,%2,%3}, {%4,%5,%6,%7}, {%8,%9}, {%0,%1,%2,%3};"
        : "+f"(c[0]), "+f"(c[1]), "+f"(c[2]), "+f"(c[3])
        : "r"(a[0]), "r"(a[1]), "r"(a[2]), "r"(a[3]), "r"(b0), "r"(b1));
}

__device__ __forceinline__ __half hhi(float x) { return __float2half_rn(x); }

// ---------------------------------------------------------------------------
// Fused prep kernel: one launch does
//   blocks [0, 350):    W0 [800][400] -> W0t fp16 [448][800]   (25 x 14 tiles)
//   blocks [350, 546):  W1 [400][400] -> W1t fp16 [448][448]   (14 x 14 tiles)
//   blocks [546, 559):  colsum of W1 -> g_cs1[0..400)          (13 col-groups)
// ---------------------------------------------------------------------------
__device__ __forceinline__ void transpose_tile(
    const float* __restrict__ W, __half* __restrict__ T,
    int kt, int nt, int K, int N, int KP)
{
    __shared__ float t[32][33];
    const int tx = threadIdx.x & 31;
    const int ty = threadIdx.x >> 5;

    #pragma unroll
    for (int i = 0; i < 4; i++) {
        const int k = kt + ty + i * 8;
        float v = 0.f;
        if (k < K && nt + tx < N) v = W[(size_t)k * N + nt + tx];
        t[ty + i * 8][tx] = v;
    }
    __syncthreads();
    #pragma unroll
    for (int i = 0; i < 4; i++) {
        const int n = nt + ty + i * 8;
        const int k = kt + tx;
        T[(size_t)n * KP + k] = hhi(t[tx][ty + i * 8]);
    }
}

__global__ __launch_bounds__(256) void prep_kernel(
    const float* __restrict__ W0, const float* __restrict__ W1)
{
    const int bid = blockIdx.x;
    if (bid < 350) {
        const int kt = (bid % 25) * 32;
        const int nt = (bid / 25) * 32;
        transpose_tile(W0, g_W0t, kt, nt, D_, H_, KP1);
    } else if (bid < 546) {
        const int b2 = bid - 350;
        const int kt = (b2 % 14) * 32;
        const int nt = (b2 / 14) * 32;
        transpose_tile(W1, g_W1t, kt, nt, H_, H_, KP2);
    } else {
        // colsum: 32 columns per block, 8 row-groups of 50 rows each
        __shared__ float ps[8][32];
        const int col = threadIdx.x & 31;
        const int rg  = threadIdx.x >> 5;
        const int n   = (bid - 546) * 32 + col;
        float s = 0.f;
        if (n < H_) {
            const int r0 = rg * 50;
            for (int r = r0; r < r0 + 50; r++) s += W1[(size_t)r * H_ + n];
        }
        ps[rg][col] = s;
        __syncthreads();
        if (rg == 0 && n < H_) {
            float tot = 0.f;
            #pragma unroll
            for (int g = 0; g < 8; g++) tot += ps[g][col];
            g_cs1[n] = tot;
        }
    }
}

// ---------------------------------------------------------------------------
// Kernel B: gather + FM, warp-per-sample, float4 vectorized, shfl reductions.
// ---------------------------------------------------------------------------
__global__ __launch_bounds__(256) void gather_fm_kernel(
    const int*   __restrict__ feats,
    const float* __restrict__ values,
    const float* __restrict__ weights,
    const float* __restrict__ embedding,
    const float* __restrict__ bias)
{
    const int wid  = threadIdx.x >> 5;
    const int lane = threadIdx.x & 31;
    const int b    = blockIdx.x * 8 + wid;
    const int base = b * NF_;

    // ---- first order: lane covers f=lane and f=lane+32
    float fw = weights[feats[base + lane]] * values[base + lane];
    if (lane < NF_ - 32)
        fw += weights[feats[base + 32 + lane]] * values[base + 32 + lane];

    // ---- main sweep: 200 float4s (50 features x 4 quads)
    float a1[4] = {0.f, 0.f, 0.f, 0.f};
    float a2[4] = {0.f, 0.f, 0.f, 0.f};

    __half* xrow = g_X + (size_t)b * KP1;

    #pragma unroll
    for (int j = 0; j < 7; j++) {
        const int i4 = j * 32 + lane;
        if (j < 6 || lane < 8) {
            const int f  = i4 >> 2;
            const int k4 = (i4 & 3) << 2;
            const int feat = feats[base + f];
            const float v  = values[base + f];
            const float4 e = *reinterpret_cast<const float4*>(
                embedding + (size_t)feat * KE_ + k4);
            __half2 h01, h23;
            h01.x = hhi(e.x); h01.y = hhi(e.y);
            h23.x = hhi(e.z); h23.y = hhi(e.w);
            uint2 pk;
            pk.x = *reinterpret_cast<uint32_t*>(&h01);
            pk.y = *reinterpret_cast<uint32_t*>(&h23);
            *reinterpret_cast<uint2*>(xrow + i4 * 4) = pk;
            const float e0 = e.x * v, e1 = e.y * v, e2 = e.z * v, e3 = e.w * v;
            a1[0] += e0; a2[0] += e0 * e0;
            a1[1] += e1; a2[1] += e1 * e1;
            a1[2] += e2; a2[2] += e2 * e2;
            a1[3] += e3; a2[3] += e3 * e3;
        }
    }

    // ---- reduce a1/a2 across the 8 lanes sharing (lane&3)
    #pragma unroll
    for (int o = 4; o <= 16; o <<= 1) {
        #pragma unroll
        for (int q = 0; q < 4; q++) {
            a1[q] += __shfl_xor_sync(0xffffffffu, a1[q], o);
            a2[q] += __shfl_xor_sync(0xffffffffu, a2[q], o);
        }
    }
    float sec = 0.f;
    #pragma unroll
    for (int q = 0; q < 4; q++) sec += a1[q] * a1[q] - a2[q];
    sec += __shfl_xor_sync(0xffffffffu, sec, 1);
    sec += __shfl_xor_sync(0xffffffffu, sec, 2);

    #pragma unroll
    for (int o = 1; o <= 16; o <<= 1) fw += __shfl_xor_sync(0xffffffffu, fw, o);

    if (lane == 0) {
        g_ZP[b] = fw + bias[0] + 0.5f * sec;
        g_S[b]  = 0.f;
    }
}

// ---------------------------------------------------------------------------
// Kernel C: single-term fp16 tensor GEMM, CTA 256x64, 512 thr (16 warps 8Mx2N,
// warp tile 32x32), BK=32, 2-stage cp.async double buffer, f32 accumulate.
// mode 0 (GEMM1): x=relu(acc+b0); store fp16(x - max(b0,0)) -> H0c stride KP2
// mode 1 (GEMM2): x=relu(acc + b0p*cs1[c] + b1); atomicAdd rowsum(x*W2) -> g_S
// ---------------------------------------------------------------------------
#define ASTR 40                 // smem row stride (fp16 units)
#define A_BYTES 20480           // 256*40*2
#define B_BYTES 5120            // 64*40*2
#define STAGE_BYTES (A_BYTES + B_BYTES)
#define SMEM_BYTES (2 * STAGE_BYTES)

__global__ __launch_bounds__(NTHR) void gemm_fp16(
    const __half* __restrict__ A,
    const __half* __restrict__ Bw,
    const float* __restrict__ biasp,    // own layer bias (b0 or b1)
    const float* __restrict__ prevbp,   // previous layer bias (b0) for mode 1
    const float* __restrict__ W2,       // mode 1 only
    int KP, int nchunks, int mode,
    __half* __restrict__ outH)          // mode 0 only
{
    extern __shared__ char smem[];
    const uint32_t sbase = smem_u32(smem);

    const int tid  = threadIdx.x;
    const int lane = tid & 31;
    const int w    = tid >> 5;
    const int wm   = (w >> 1) << 5;   // warp M offset (0..224)
    const int wn   = (w & 1) << 5;    // warp N offset (0,32)
    const int grp  = lane >> 2;
    const int thg  = lane & 3;
    const int row0 = blockIdx.y * TM;
    const int col0 = blockIdx.x * TN;

    const int sub = lane >> 3;
    const int l8  = lane & 7;

    float acc[2][4][4];
    #pragma unroll
    for (int i = 0; i < 2; i++)
        #pragma unroll
        for (int j = 0; j < 4; j++)
            #pragma unroll
            for (int q = 0; q < 4; q++) acc[i][j][q] = 0.f;

    auto load_chunk = [&](int c, int s) {
        const int k0 = c * BKC;
        const uint32_t stb = sbase + s * STAGE_BYTES;
        #pragma unroll
        for (int i = 0; i < 2; i++) {
            const int v  = tid + (i << 9);          // 1024 vectors over 512 thr
            const int r  = v >> 2;
            const int c8 = (v & 3) << 3;
            const uint32_t so = (uint32_t)(r * ASTR + c8) * 2;
            CP16(stb + so, A + (size_t)(row0 + r) * KP + k0 + c8);
        }
        if (tid < 256) {
            const int r  = tid >> 2;
            const int c8 = (tid & 3) << 3;
            const uint32_t so = (uint32_t)(r * ASTR + c8) * 2;
            CP16(stb + A_BYTES + so, Bw + (size_t)(col0 + r) * KP + k0 + c8);
        }
        CP_COMMIT();
    };

    load_chunk(0, 0);

    for (int c = 0; c < nchunks; c++) {
        const int s = c & 1;
        if (c + 1 < nchunks) { load_chunk(c + 1, s ^ 1); CP_WAIT(1); }
        else                 { CP_WAIT(0); }
        __syncthreads();

        const uint32_t stb = sbase + s * STAGE_BYTES;
        #pragma unroll
        for (int kk = 0; kk < BKC; kk += 16) {
            uint32_t ah[2][4], bh[2][4];
            #pragma unroll
            for (int i = 0; i < 2; i++) {
                const int row = wm + i * 16 + ((sub & 1) << 3) + l8;
                const int kc  = kk + ((sub >> 1) << 3);
                LDSM4(ah[i], stb + (uint32_t)(row * ASTR + kc) * 2);
            }
            #pragma unroll
            for (int jj = 0; jj < 2; jj++) {
                const int row = wn + jj * 16 + ((sub >> 1) << 3) + l8;
                const int kc  = kk + ((sub & 1) << 3);
                LDSM4(bh[jj], stb + A_BYTES + (uint32_t)(row * ASTR + kc) * 2);
            }
            #pragma unroll
            for (int i = 0; i < 2; i++)
                #pragma unroll
                for (int j = 0; j < 4; j++)
                    mma16f(acc[i][j], ah[i],
                           bh[j >> 1][(j & 1) * 2], bh[j >> 1][(j & 1) * 2 + 1]);
        }
        __syncthreads();
    }

    const float bv  = *biasp;
    if (mode == 0) {
        // H0c = relu(acc + b0) - max(b0, 0), fp16, stride KP2
        const float bp = fmaxf(bv, 0.f);
        #pragma unroll
        for (int i = 0; i < 2; i++) {
            #pragma unroll
            for (int j = 0; j < 4; j++) {
                const int r = row0 + wm + i * 16 + grp;
                const int cc = col0 + wn + j * 8 + (thg << 1);
                #pragma unroll
                for (int half = 0; half < 2; half++) {
                    const int rr = r + half * 8;
                    const float x0 = fmaxf(acc[i][j][half * 2]     + bv, 0.f) - bp;
                    const float x1 = fmaxf(acc[i][j][half * 2 + 1] + bv, 0.f) - bp;
                    __half2 hp; hp.x = hhi(x0); hp.y = hhi(x1);
                    *reinterpret_cast<__half2*>(outH + (size_t)rr * KP2 + cc) = hp;
                }
            }
        }
    } else {
        // H1 = relu(acc + b0p*cs1[c] + b1); rowsum(H1 * W2) -> atomicAdd(g_S)
        const float bp = fmaxf(*prevbp, 0.f);
        float rs[2][2] = {{0.f, 0.f}, {0.f, 0.f}};
        #pragma unroll
        for (int i = 0; i < 2; i++) {
            #pragma unroll
            for (int j = 0; j < 4; j++) {
                const int cc = col0 + wn + j * 8 + (thg << 1);
                const float w2a = (cc     < H_) ? W2[cc]     : 0.f;
                const float w2b = (cc + 1 < H_) ? W2[cc + 1] : 0.f;
                const float ca = (cc     < H_) ? g_cs1[cc]     : 0.f;
                const float cb = (cc + 1 < H_) ? g_cs1[cc + 1] : 0.f;
                #pragma unroll
                for (int half = 0; half < 2; half++) {
                    const float x0 = fmaxf(acc[i][j][half * 2]     + bp * ca + bv, 0.f);
                    const float x1 = fmaxf(acc[i][j][half * 2 + 1] + bp * cb + bv, 0.f);
                    rs[i][half] += x0 * w2a + x1 * w2b;
                }
            }
        }
        #pragma unroll
        for (int i = 0; i < 2; i++)
            #pragma unroll
            for (int half = 0; half < 2; half++) {
                float v = rs[i][half];
                v += __shfl_xor_sync(0xffffffffu, v, 1);
                v += __shfl_xor_sync(0xffffffffu, v, 2);
                if (thg == 0) {
                    const int rr = row0 + wm + i * 16 + grp + half * 8;
                    atomicAdd(&g_S[rr], v);
                }
            }
    }
}

// ---------------------------------------------------------------------------
// Kernel D: out = sigmoid(ZP + relu(S + b2))
// ---------------------------------------------------------------------------
__global__ __launch_bounds__(256) void final_small(
    const float* __restrict__ b2, float* __restrict__ out)
{
    const int b = blockIdx.x * 256 + threadIdx.x;
    if (b >= B_) return;
    const float hi = fmaxf(g_S[b] + b2[0], 0.f);
    const float z  = g_ZP[b] + hi;
    out[b] = 1.f / (1.f + expf(-z));
}

// ---------------------------------------------------------------------------
extern "C" void kernel_launch(void* const* d_in, const int* in_sizes, int n_in,
                              void* d_out, int out_size)
{
    const int*   feats   = (const int*)  d_in[1];
    const float* values  = (const float*)d_in[2];
    const float* bias    = (const float*)d_in[3];
    const float* weights = (const float*)d_in[4];
    const float* emb     = (const float*)d_in[5];
    const float* W0      = (const float*)d_in[6];
    const float* b0      = (const float*)d_in[7];
    const float* W1      = (const float*)d_in[8];
    const float* b1      = (const float*)d_in[9];
    const float* W2      = (const float*)d_in[10];
    const float* b2      = (const float*)d_in[11];
    float* out = (float*)d_out;

    __half *X, *W0t, *W1t, *H0c;
    cudaGetSymbolAddress((void**)&X,    g_X);
    cudaGetSymbolAddress((void**)&W0t,  g_W0t);
    cudaGetSymbolAddress((void**)&W1t,  g_W1t);
    cudaGetSymbolAddress((void**)&H0c,  g_H0c);

    static int smem_set = 0;
    if (!smem_set) {
        cudaFuncSetAttribute(gemm_fp16, cudaFuncAttributeMaxDynamicSharedMemorySize,
                             SMEM_BYTES);
        smem_set = 1;
    }

    // 0) fused weight prep (both transposes + colsum) in ONE launch
    prep_kernel<<<559, 256>>>(W0, W1);

    // 1) gather + FM + X fp16 (+ zero g_S): warp per sample
    gather_fm_kernel<<<B_ / 8, 256>>>(feats, values, weights, emb, bias);

    // 2) H0c = relu(X @ W0 + b0) - b0p  -> fp16 [16384][448]
    {
        dim3 grid(NP_ / TN, B_ / TM);
        gemm_fp16<<<grid, NTHR, SMEM_BYTES>>>(X, W0t, b0, nullptr, nullptr,
                                              KP1, KP1 / BKC, 0, H0c);
    }
    // 3) g_S += rowsum(relu(H0c @ W1 + b0p*cs1 + b1) * W2)  (fused GEMV)
    {
        dim3 grid(NP_ / TN, B_ / TM);
        gemm_fp16<<<grid, NTHR, SMEM_BYTES>>>(H0c, W1t, b1, b0, W2,
                                              KP2, KP2 / BKC, 1, nullptr);
    }
    // 4) out = sigmoid(ZP + relu(S + b2))
    final_small<<<(B_ + 255) / 256, 256>>>(b2, out);
}

// round 11
// speedup vs baseline: 2.6613x; 1.0611x over previous
#include <cuda_runtime.h>
#include <cuda_fp16.h>
#include <math.h>
#include <stdint.h>

// ---------------- problem constants ----------------
#define B_   16384
#define NF_  50
#define KE_  16
#define D_   800     // NF_*KE_
#define H_   400
#define KP1  800     // K for GEMM1 (25 * 32, exact)
#define KP2  448     // padded K for GEMM2 (14 * 32)
#define NP_  448     // padded N (= 7 * 64)
#define TM   256
#define TN   64
#define BKC  32
#define NTHR 512
#define NSTG 3       // cp.async pipeline stages (free: RF limits to 2 CTAs/SM)

// ---------------- scratch globals ----------------
__device__ __half g_X   [B_ * KP1];   // gathered embeddings fp16
__device__ __half g_W0t [NP_ * KP1];  // W0^T fp16 [448][800], rows>=400 zero
__device__ __half g_W1t [NP_ * KP2];  // W1^T fp16 [448][448]
__device__ __half g_H0c [B_ * KP2];   // centered H0 (H0 - b0plus), fp16
__device__ float g_cs1[NP_];          // colsum of W1 (cols >=400 unused)
__device__ float g_S  [B_];           // fused GEMV accumulator
__device__ float g_ZP [B_];           // first + second (+bias)

// ---------------- PTX helpers ----------------
__device__ __forceinline__ uint32_t smem_u32(const void* p) {
    uint32_t a;
    asm("{ .reg .u64 t; cvta.to.shared.u64 t, %1; cvt.u32.u64 %0, t; }"
        : "=r"(a) : "l"(p));
    return a;
}

#define CP16(dst, src) \
    asm volatile("cp.async.cg.shared.global [%0], [%1], 16;" \
                 :: "r"(dst), "l"(src) : "memory")
#define CP_COMMIT() asm volatile("cp.async.commit_group;" ::: "memory")
#define CP_WAIT(n)  asm volatile("cp.async.wait_group %0;" :: "n"(n) : "memory")

#define LDSM4(r, addr) \
    asm volatile("ldmatrix.sync.aligned.m8n8.x4.shared.b16 {%0,%1,%2,%3}, [%4];" \
        : "=r"((r)[0]), "=r"((r)[1]), "=r"((r)[2]), "=r"((r)[3]) : "r"(addr))

__device__ __forceinline__ void mma16f(float* c, const uint32_t* a,
                                       uint32_t b0, uint32_t b1) {
    asm volatile(
        "mma.sync.aligned.m16n8k16.row.col.f32.f16.f16.f32 "
        "{%0,%1,%2,%3}, {%4,%5,%6,%7}, {%8,%9}, {%0,%1,%2,%3};"
        : "+f"(c[0]), "+f"(c[1]), "+f"(c[2]), "+f"(c[3])
        : "r"(a[0]), "r"(a[1]), "r"(a[2]), "r"(a[3]), "r"(b0), "r"(b1));
}

__device__ __forceinline__ __half hhi(float x) { return __float2half_rn(x); }

// ---------------------------------------------------------------------------
// Fused prep kernel: one launch does
//   blocks [0, 350):    W0 [800][400] -> W0t fp16 [448][800]   (25 x 14 tiles)
//   blocks [350, 546):  W1 [400][400] -> W1t fp16 [448][448]   (14 x 14 tiles)
//   blocks [546, 559):  colsum of W1 -> g_cs1[0..400)          (13 col-groups)
// ---------------------------------------------------------------------------
__device__ __forceinline__ void transpose_tile(
    const float* __restrict__ W, __half* __restrict__ T,
    int kt, int nt, int K, int N, int KP)
{
    __shared__ float t[32][33];
    const int tx = threadIdx.x & 31;
    const int ty = threadIdx.x >> 5;

    #pragma unroll
    for (int i = 0; i < 4; i++) {
        const int k = kt + ty + i * 8;
        float v = 0.f;
        if (k < K && nt + tx < N) v = W[(size_t)k * N + nt + tx];
        t[ty + i * 8][tx] = v;
    }
    __syncthreads();
    #pragma unroll
    for (int i = 0; i < 4; i++) {
        const int n = nt + ty + i * 8;
        const int k = kt + tx;
        T[(size_t)n * KP + k] = hhi(t[tx][ty + i * 8]);
    }
}

__global__ __launch_bounds__(256) void prep_kernel(
    const float* __restrict__ W0, const float* __restrict__ W1)
{
    const int bid = blockIdx.x;
    if (bid < 350) {
        const int kt = (bid % 25) * 32;
        const int nt = (bid / 25) * 32;
        transpose_tile(W0, g_W0t, kt, nt, D_, H_, KP1);
    } else if (bid < 546) {
        const int b2 = bid - 350;
        const int kt = (b2 % 14) * 32;
        const int nt = (b2 / 14) * 32;
        transpose_tile(W1, g_W1t, kt, nt, H_, H_, KP2);
    } else {
        // colsum: 32 columns per block, 8 row-groups of 50 rows each
        __shared__ float ps[8][32];
        const int col = threadIdx.x & 31;
        const int rg  = threadIdx.x >> 5;
        const int n   = (bid - 546) * 32 + col;
        float s = 0.f;
        if (n < H_) {
            const int r0 = rg * 50;
            for (int r = r0; r < r0 + 50; r++) s += W1[(size_t)r * H_ + n];
        }
        ps[rg][col] = s;
        __syncthreads();
        if (rg == 0 && n < H_) {
            float tot = 0.f;
            #pragma unroll
            for (int g = 0; g < 8; g++) tot += ps[g][col];
            g_cs1[n] = tot;
        }
    }
}

// ---------------------------------------------------------------------------
// Kernel B: gather + FM, warp-per-sample, float4 vectorized, shfl reductions.
// ---------------------------------------------------------------------------
__global__ __launch_bounds__(256) void gather_fm_kernel(
    const int*   __restrict__ feats,
    const float* __restrict__ values,
    const float* __restrict__ weights,
    const float* __restrict__ embedding,
    const float* __restrict__ bias)
{
    const int wid  = threadIdx.x >> 5;
    const int lane = threadIdx.x & 31;
    const int b    = blockIdx.x * 8 + wid;
    const int base = b * NF_;

    // ---- first order: lane covers f=lane and f=lane+32
    float fw = weights[feats[base + lane]] * values[base + lane];
    if (lane < NF_ - 32)
        fw += weights[feats[base + 32 + lane]] * values[base + 32 + lane];

    // ---- main sweep: 200 float4s (50 features x 4 quads)
    float a1[4] = {0.f, 0.f, 0.f, 0.f};
    float a2[4] = {0.f, 0.f, 0.f, 0.f};

    __half* xrow = g_X + (size_t)b * KP1;

    #pragma unroll
    for (int j = 0; j < 7; j++) {
        const int i4 = j * 32 + lane;
        if (j < 6 || lane < 8) {
            const int f  = i4 >> 2;
            const int k4 = (i4 & 3) << 2;
            const int feat = feats[base + f];
            const float v  = values[base + f];
            const float4 e = *reinterpret_cast<const float4*>(
                embedding + (size_t)feat * KE_ + k4);
            __half2 h01, h23;
            h01.x = hhi(e.x); h01.y = hhi(e.y);
            h23.x = hhi(e.z); h23.y = hhi(e.w);
            uint2 pk;
            pk.x = *reinterpret_cast<uint32_t*>(&h01);
            pk.y = *reinterpret_cast<uint32_t*>(&h23);
            *reinterpret_cast<uint2*>(xrow + i4 * 4) = pk;
            const float e0 = e.x * v, e1 = e.y * v, e2 = e.z * v, e3 = e.w * v;
            a1[0] += e0; a2[0] += e0 * e0;
            a1[1] += e1; a2[1] += e1 * e1;
            a1[2] += e2; a2[2] += e2 * e2;
            a1[3] += e3; a2[3] += e3 * e3;
        }
    }

    // ---- reduce a1/a2 across the 8 lanes sharing (lane&3)
    #pragma unroll
    for (int o = 4; o <= 16; o <<= 1) {
        #pragma unroll
        for (int q = 0; q < 4; q++) {
            a1[q] += __shfl_xor_sync(0xffffffffu, a1[q], o);
            a2[q] += __shfl_xor_sync(0xffffffffu, a2[q], o);
        }
    }
    float sec = 0.f;
    #pragma unroll
    for (int q = 0; q < 4; q++) sec += a1[q] * a1[q] - a2[q];
    sec += __shfl_xor_sync(0xffffffffu, sec, 1);
    sec += __shfl_xor_sync(0xffffffffu, sec, 2);

    #pragma unroll
    for (int o = 1; o <= 16; o <<= 1) fw += __shfl_xor_sync(0xffffffffu, fw, o);

    if (lane == 0) {
        g_ZP[b] = fw + bias[0] + 0.5f * sec;
        g_S[b]  = 0.f;
    }
}

// ---------------------------------------------------------------------------
// Kernel C: single-term fp16 tensor GEMM, CTA 256x64, 512 thr (16 warps 8Mx2N,
// warp tile 32x32), BK=32, 3-stage cp.async pipeline, ONE barrier per chunk.
// mode 0 (GEMM1): x=relu(acc+b0); store fp16(x - max(b0,0)) -> H0c stride KP2
// mode 1 (GEMM2): x=relu(acc + b0p*cs1[c] + b1); atomicAdd rowsum(x*W2) -> g_S
// ---------------------------------------------------------------------------
#define ASTR 40                 // smem row stride (fp16 units)
#define A_BYTES 20480           // 256*40*2
#define B_BYTES 5120            // 64*40*2
#define STAGE_BYTES (A_BYTES + B_BYTES)
#define SMEM_BYTES (NSTG * STAGE_BYTES)

__global__ __launch_bounds__(NTHR) void gemm_fp16(
    const __half* __restrict__ A,
    const __half* __restrict__ Bw,
    const float* __restrict__ biasp,    // own layer bias (b0 or b1)
    const float* __restrict__ prevbp,   // previous layer bias (b0) for mode 1
    const float* __restrict__ W2,       // mode 1 only
    int KP, int nchunks, int mode,
    __half* __restrict__ outH)          // mode 0 only
{
    extern __shared__ char smem[];
    const uint32_t sbase = smem_u32(smem);

    const int tid  = threadIdx.x;
    const int lane = tid & 31;
    const int w    = tid >> 5;
    const int wm   = (w >> 1) << 5;   // warp M offset (0..224)
    const int wn   = (w & 1) << 5;    // warp N offset (0,32)
    const int grp  = lane >> 2;
    const int thg  = lane & 3;
    const int row0 = blockIdx.y * TM;
    const int col0 = blockIdx.x * TN;

    const int sub = lane >> 3;
    const int l8  = lane & 7;

    float acc[2][4][4];
    #pragma unroll
    for (int i = 0; i < 2; i++)
        #pragma unroll
        for (int j = 0; j < 4; j++)
            #pragma unroll
            for (int q = 0; q < 4; q++) acc[i][j][q] = 0.f;

    auto load_chunk = [&](int c, int s) {
        const int k0 = c * BKC;
        const uint32_t stb = sbase + s * STAGE_BYTES;
        #pragma unroll
        for (int i = 0; i < 2; i++) {
            const int v  = tid + (i << 9);          // 1024 vectors over 512 thr
            const int r  = v >> 2;
            const int c8 = (v & 3) << 3;
            const uint32_t so = (uint32_t)(r * ASTR + c8) * 2;
            CP16(stb + so, A + (size_t)(row0 + r) * KP + k0 + c8);
        }
        if (tid < 256) {
            const int r  = tid >> 2;
            const int c8 = (tid & 3) << 3;
            const uint32_t so = (uint32_t)(r * ASTR + c8) * 2;
            CP16(stb + A_BYTES + so, Bw + (size_t)(col0 + r) * KP + k0 + c8);
        }
    };

    // prologue: fill NSTG-1 stages
    #pragma unroll
    for (int p = 0; p < NSTG - 1; p++) {
        load_chunk(p, p);
        CP_COMMIT();
    }

    for (int c = 0; c < nchunks; c++) {
        CP_WAIT(NSTG - 2);           // chunk c resident
        __syncthreads();             // all warps done with stage being refilled

        if (c + NSTG - 1 < nchunks) load_chunk(c + NSTG - 1, (c + NSTG - 1) % NSTG);
        CP_COMMIT();                 // exactly one group per iteration

        const uint32_t stb = sbase + (c % NSTG) * STAGE_BYTES;
        #pragma unroll
        for (int kk = 0; kk < BKC; kk += 16) {
            uint32_t ah[2][4], bh[2][4];
            #pragma unroll
            for (int i = 0; i < 2; i++) {
                const int row = wm + i * 16 + ((sub & 1) << 3) + l8;
                const int kc  = kk + ((sub >> 1) << 3);
                LDSM4(ah[i], stb + (uint32_t)(row * ASTR + kc) * 2);
            }
            #pragma unroll
            for (int jj = 0; jj < 2; jj++) {
                const int row = wn + jj * 16 + ((sub >> 1) << 3) + l8;
                const int kc  = kk + ((sub & 1) << 3);
                LDSM4(bh[jj], stb + A_BYTES + (uint32_t)(row * ASTR + kc) * 2);
            }
            #pragma unroll
            for (int i = 0; i < 2; i++)
                #pragma unroll
                for (int j = 0; j < 4; j++)
                    mma16f(acc[i][j], ah[i],
                           bh[j >> 1][(j & 1) * 2], bh[j >> 1][(j & 1) * 2 + 1]);
        }
    }

    const float bv  = *biasp;
    if (mode == 0) {
        // H0c = relu(acc + b0) - max(b0, 0), fp16, stride KP2
        const float bp = fmaxf(bv, 0.f);
        #pragma unroll
        for (int i = 0; i < 2; i++) {
            #pragma unroll
            for (int j = 0; j < 4; j++) {
                const int r = row0 + wm + i * 16 + grp;
                const int cc = col0 + wn + j * 8 + (thg << 1);
                #pragma unroll
                for (int half = 0; half < 2; half++) {
                    const int rr = r + half * 8;
                    const float x0 = fmaxf(acc[i][j][half * 2]     + bv, 0.f) - bp;
                    const float x1 = fmaxf(acc[i][j][half * 2 + 1] + bv, 0.f) - bp;
                    __half2 hp; hp.x = hhi(x0); hp.y = hhi(x1);
                    *reinterpret_cast<__half2*>(outH + (size_t)rr * KP2 + cc) = hp;
                }
            }
        }
    } else {
        // H1 = relu(acc + b0p*cs1[c] + b1); rowsum(H1 * W2) -> atomicAdd(g_S)
        const float bp = fmaxf(*prevbp, 0.f);
        float rs[2][2] = {{0.f, 0.f}, {0.f, 0.f}};
        #pragma unroll
        for (int i = 0; i < 2; i++) {
            #pragma unroll
            for (int j = 0; j < 4; j++) {
                const int cc = col0 + wn + j * 8 + (thg << 1);
                const float w2a = (cc     < H_) ? W2[cc]     : 0.f;
                const float w2b = (cc + 1 < H_) ? W2[cc + 1] : 0.f;
                const float ca = (cc     < H_) ? g_cs1[cc]     : 0.f;
                const float cb = (cc + 1 < H_) ? g_cs1[cc + 1] : 0.f;
                #pragma unroll
                for (int half = 0; half < 2; half++) {
                    const float x0 = fmaxf(acc[i][j][half * 2]     + bp * ca + bv, 0.f);
                    const float x1 = fmaxf(acc[i][j][half * 2 + 1] + bp * cb + bv, 0.f);
                    rs[i][half] += x0 * w2a + x1 * w2b;
                }
            }
        }
        #pragma unroll
        for (int i = 0; i < 2; i++)
            #pragma unroll
            for (int half = 0; half < 2; half++) {
                float v = rs[i][half];
                v += __shfl_xor_sync(0xffffffffu, v, 1);
                v += __shfl_xor_sync(0xffffffffu, v, 2);
                if (thg == 0) {
                    const int rr = row0 + wm + i * 16 + grp + half * 8;
                    atomicAdd(&g_S[rr], v);
                }
            }
    }
}

// ---------------------------------------------------------------------------
// Kernel D: out = sigmoid(ZP + relu(S + b2))
// ---------------------------------------------------------------------------
__global__ __launch_bounds__(256) void final_small(
    const float* __restrict__ b2, float* __restrict__ out)
{
    const int b = blockIdx.x * 256 + threadIdx.x;
    if (b >= B_) return;
    const float hi = fmaxf(g_S[b] + b2[0], 0.f);
    const float z  = g_ZP[b] + hi;
    out[b] = 1.f / (1.f + expf(-z));
}

// ---------------------------------------------------------------------------
extern "C" void kernel_launch(void* const* d_in, const int* in_sizes, int n_in,
                              void* d_out, int out_size)
{
    const int*   feats   = (const int*)  d_in[1];
    const float* values  = (const float*)d_in[2];
    const float* bias    = (const float*)d_in[3];
    const float* weights = (const float*)d_in[4];
    const float* emb     = (const float*)d_in[5];
    const float* W0      = (const float*)d_in[6];
    const float* b0      = (const float*)d_in[7];
    const float* W1      = (const float*)d_in[8];
    const float* b1      = (const float*)d_in[9];
    const float* W2      = (const float*)d_in[10];
    const float* b2      = (const float*)d_in[11];
    float* out = (float*)d_out;

    __half *X, *W0t, *W1t, *H0c;
    cudaGetSymbolAddress((void**)&X,    g_X);
    cudaGetSymbolAddress((void**)&W0t,  g_W0t);
    cudaGetSymbolAddress((void**)&W1t,  g_W1t);
    cudaGetSymbolAddress((void**)&H0c,  g_H0c);

    static int smem_set = 0;
    if (!smem_set) {
        cudaFuncSetAttribute(gemm_fp16, cudaFuncAttributeMaxDynamicSharedMemorySize,
                             SMEM_BYTES);
        smem_set = 1;
    }

    // 0) fused weight prep (both transposes + colsum) in ONE launch
    prep_kernel<<<559, 256>>>(W0, W1);

    // 1) gather + FM + X fp16 (+ zero g_S): warp per sample
    gather_fm_kernel<<<B_ / 8, 256>>>(feats, values, weights, emb, bias);

    // 2) H0c = relu(X @ W0 + b0) - b0p  -> fp16 [16384][448]
    {
        dim3 grid(NP_ / TN, B_ / TM);
        gemm_fp16<<<grid, NTHR, SMEM_BYTES>>>(X, W0t, b0, nullptr, nullptr,
                                              KP1, KP1 / BKC, 0, H0c);
    }
    // 3) g_S += rowsum(relu(H0c @ W1 + b0p*cs1 + b1) * W2)  (fused GEMV)
    {
        dim3 grid(NP_ / TN, B_ / TM);
        gemm_fp16<<<grid, NTHR, SMEM_BYTES>>>(H0c, W1t, b1, b0, W2,
                                              KP2, KP2 / BKC, 1, nullptr);
    }
    // 4) out = sigmoid(ZP + relu(S + b2))
    final_small<<<(B_ + 255) / 256, 256>>>(b2, out);
}